// round 1
// baseline (speedup 1.0000x reference)
#include <cuda_runtime.h>

#define Bb 2
#define Ss 2048
#define Dd 1024
#define Hh 16
#define HDd 64
#define QKV_ELEMS (Bb*Hh*Ss*HDd)   // 4194304

// scratch: [0]=q, [1]=k, [2]=v (each [B,H,S,HD]), [3]=concat [B*S, D]
static __device__ float g_scratch[4ull * (unsigned long long)QKV_ELEMS];

// ---------------------------------------------------------------------------
// Tiled SGEMM: C = A[4096,1024] * W[1024,1024] + bias
// 128x128 tile, BK=8, 256 threads, 8x8 micro-tile per thread.
// SPLIT=1 stores to [B,H,S,HD] split-head layout; SPLIT=0 row-major.
// ---------------------------------------------------------------------------
template<int SPLIT>
__device__ __forceinline__ void gemm_tile(const float* __restrict__ A,
                                          const float* __restrict__ W,
                                          const float* __restrict__ bias,
                                          float* __restrict__ C)
{
    __shared__ float As[8][128];
    __shared__ float Bs[8][128];

    const int tid = threadIdx.x;
    const int tx = tid & 15;
    const int ty = tid >> 4;
    const int m0 = blockIdx.y * 128;
    const int n0 = blockIdx.x * 128;

    // A tile load: 128 rows x 8 cols, one float4 per thread (transposed store)
    const int arow = tid >> 1;            // 0..127
    const int acol = (tid & 1) << 2;      // 0 or 4
    // W tile load: 8 rows x 128 cols, one float4 per thread (coalesced)
    const int wrow = tid >> 5;            // 0..7
    const int wcol = (tid & 31) << 2;     // 0..124

    const float* Aptr = A + (size_t)(m0 + arow) * Dd + acol;
    const float* Wptr = W + (size_t)wrow * Dd + n0 + wcol;

    float acc[8][8];
#pragma unroll
    for (int i = 0; i < 8; i++)
#pragma unroll
        for (int j = 0; j < 8; j++) acc[i][j] = 0.f;

    for (int k0 = 0; k0 < Dd; k0 += 8) {
        float4 a4 = *(const float4*)(Aptr + k0);
        float4 w4 = *(const float4*)(Wptr + (size_t)k0 * Dd);
        As[acol + 0][arow] = a4.x;
        As[acol + 1][arow] = a4.y;
        As[acol + 2][arow] = a4.z;
        As[acol + 3][arow] = a4.w;
        *(float4*)&Bs[wrow][wcol] = w4;
        __syncthreads();
#pragma unroll
        for (int k = 0; k < 8; k++) {
            float a[8], b[8];
            *(float4*)(a)     = *(const float4*)&As[k][ty * 4];
            *(float4*)(a + 4) = *(const float4*)&As[k][64 + ty * 4];
            *(float4*)(b)     = *(const float4*)&Bs[k][tx * 4];
            *(float4*)(b + 4) = *(const float4*)&Bs[k][64 + tx * 4];
#pragma unroll
            for (int i = 0; i < 8; i++)
#pragma unroll
                for (int j = 0; j < 8; j++)
                    acc[i][j] = fmaf(a[i], b[j], acc[i][j]);
        }
        __syncthreads();
    }

#pragma unroll
    for (int i = 0; i < 8; i++) {
        int r = m0 + ((i < 4) ? (ty * 4 + i) : (64 + ty * 4 + (i - 4)));
#pragma unroll
        for (int j = 0; j < 8; j++) {
            int c = n0 + ((j < 4) ? (tx * 4 + j) : (64 + tx * 4 + (j - 4)));
            float v = acc[i][j] + bias[c];
            if (SPLIT) {
                int bb = r >> 11;          // r / S
                int s  = r & 2047;         // r % S
                int h  = c >> 6;           // c / HD
                int d  = c & 63;           // c % HD
                C[(((size_t)(bb * Hh + h)) * Ss + s) * HDd + d] = v;
            } else {
                C[(size_t)r * Dd + c] = v;
            }
        }
    }
}

__global__ __launch_bounds__(256) void gemm_qkv_kernel(
    const float* __restrict__ Aq, const float* __restrict__ Ak, const float* __restrict__ Av,
    const float* __restrict__ Wq, const float* __restrict__ bq,
    const float* __restrict__ Wk, const float* __restrict__ bk,
    const float* __restrict__ Wv, const float* __restrict__ bv)
{
    const int z = blockIdx.z;
    const float* A    = (z == 0) ? Aq : ((z == 1) ? Ak : Av);
    const float* W    = (z == 0) ? Wq : ((z == 1) ? Wk : Wv);
    const float* bias = (z == 0) ? bq : ((z == 1) ? bk : bv);
    float* C = g_scratch + (size_t)z * QKV_ELEMS;
    gemm_tile<1>(A, W, bias, C);
}

__global__ __launch_bounds__(256) void gemm_out_kernel(
    const float* __restrict__ Wo, const float* __restrict__ bo,
    float* __restrict__ out)
{
    const float* A = g_scratch + (size_t)3 * QKV_ELEMS;  // concat
    gemm_tile<0>(A, Wo, bo, out);
}

// ---------------------------------------------------------------------------
// Flash attention, causal. One thread per query row (128 rows/block).
// Q row and O accumulator fully in registers; K/V tiles of 16 in shared
// (all lanes read same address -> broadcast, conflict-free).
// ---------------------------------------------------------------------------
#define BQ 128
#define BK 16

__global__ __launch_bounds__(128) void attn_kernel()
{
    const int bh  = blockIdx.y;               // b*H + h
    const int q0  = blockIdx.x * BQ;
    const int tid = threadIdx.x;
    const int q   = q0 + tid;                 // this thread's global query row

    const float* Qp = g_scratch + (size_t)bh * (Ss * HDd);
    const float* Kp = g_scratch + (size_t)QKV_ELEMS     + (size_t)bh * (Ss * HDd);
    const float* Vp = g_scratch + (size_t)2 * QKV_ELEMS + (size_t)bh * (Ss * HDd);

    __shared__ float sK[BK * HDd];
    __shared__ float sV[BK * HDd];

    float qreg[HDd];
#pragma unroll
    for (int d = 0; d < HDd; d += 4)
        *(float4*)&qreg[d] = *(const float4*)&Qp[(size_t)q * HDd + d];

    const float scale = 0.125f;               // 1/sqrt(64)
    float m = -1e30f, l = 0.f;
    float o[HDd];
#pragma unroll
    for (int d = 0; d < HDd; d++) o[d] = 0.f;

    const int kmax = q0 + BQ;                 // exclusive key bound for this block
    const int base = tid * 8;                 // coop-load offset (BK*HD=1024 floats)

    for (int t0 = 0; t0 < kmax; t0 += BK) {
        const size_t gbase = (size_t)t0 * HDd + base;
        *(float4*)(sK + base)     = *(const float4*)(Kp + gbase);
        *(float4*)(sK + base + 4) = *(const float4*)(Kp + gbase + 4);
        *(float4*)(sV + base)     = *(const float4*)(Vp + gbase);
        *(float4*)(sV + base + 4) = *(const float4*)(Vp + gbase + 4);
        __syncthreads();

        if (t0 <= q) {
            float s[BK];
            float mt = -1e30f;
#pragma unroll
            for (int j = 0; j < BK; j++) {
                float acc = 0.f;
                const float* kr = sK + j * HDd;
#pragma unroll
                for (int d = 0; d < HDd; d += 4) {
                    float4 k4 = *(const float4*)(kr + d);
                    acc = fmaf(qreg[d],     k4.x, acc);
                    acc = fmaf(qreg[d + 1], k4.y, acc);
                    acc = fmaf(qreg[d + 2], k4.z, acc);
                    acc = fmaf(qreg[d + 3], k4.w, acc);
                }
                s[j] = (t0 + j <= q) ? acc * scale : -1e30f;
                mt = fmaxf(mt, s[j]);
            }
            float mnew = fmaxf(m, mt);
            float corr = __expf(m - mnew);
            l *= corr;
#pragma unroll
            for (int d = 0; d < HDd; d++) o[d] *= corr;
#pragma unroll
            for (int j = 0; j < BK; j++) {
                float p = __expf(s[j] - mnew);
                l += p;
                const float* vr = sV + j * HDd;
#pragma unroll
                for (int d = 0; d < HDd; d += 4) {
                    float4 v4 = *(const float4*)(vr + d);
                    o[d]     = fmaf(p, v4.x, o[d]);
                    o[d + 1] = fmaf(p, v4.y, o[d + 1]);
                    o[d + 2] = fmaf(p, v4.z, o[d + 2]);
                    o[d + 3] = fmaf(p, v4.w, o[d + 3]);
                }
            }
            m = mnew;
        }
        __syncthreads();
    }

    const float inv = 1.f / l;
    const int bb = bh >> 4;                   // bh / H
    const int h  = bh & 15;                   // bh % H
    float* outp = g_scratch + (size_t)3 * QKV_ELEMS
                + ((size_t)(bb * Ss + q)) * Dd + h * HDd;
#pragma unroll
    for (int d = 0; d < HDd; d += 4) {
        float4 r;
        r.x = o[d] * inv; r.y = o[d + 1] * inv;
        r.z = o[d + 2] * inv; r.w = o[d + 3] * inv;
        *(float4*)(outp + d) = r;
    }
}

// ---------------------------------------------------------------------------
extern "C" void kernel_launch(void* const* d_in, const int* in_sizes, int n_in,
                              void* d_out, int out_size)
{
    const float* q_in = (const float*)d_in[0];
    const float* k_in = (const float*)d_in[1];
    const float* v_in = (const float*)d_in[2];
    const float* Wq   = (const float*)d_in[3];
    const float* bq   = (const float*)d_in[4];
    const float* Wk   = (const float*)d_in[5];
    const float* bk   = (const float*)d_in[6];
    const float* Wv   = (const float*)d_in[7];
    const float* bv   = (const float*)d_in[8];
    const float* Wo   = (const float*)d_in[9];
    const float* bo   = (const float*)d_in[10];
    float* out = (float*)d_out;

    dim3 gq(Dd / 128, (Bb * Ss) / 128, 3);      // 8 x 32 x 3
    gemm_qkv_kernel<<<gq, 256>>>(q_in, k_in, v_in, Wq, bq, Wk, bk, Wv, bv);

    attn_kernel<<<dim3(Ss / BQ, Bb * Hh), 128>>>();   // 16 x 32

    gemm_out_kernel<<<dim3(Dd / 128, (Bb * Ss) / 128), 256>>>(Wo, bo, out);
}

// round 3
// speedup vs baseline: 1.1589x; 1.1589x over previous
#include <cuda_runtime.h>
#include <cstdint>

#define Bb 2
#define Ss 2048
#define Dd 1024
#define Hh 16
#define HDd 64
#define QKV_ELEMS (Bb*Hh*Ss*HDd)   // 4194304
#define WT_ELEMS (Dd*Dd)           // 1048576

// scratch: [0..2]=q,k,v [B,H,S,HD]; [3]=concat [B*S,D]; then WqT,WkT,WvT,WoT
static __device__ float g_scratch[4ull * (unsigned long long)QKV_ELEMS
                                + 4ull * (unsigned long long)WT_ELEMS];

// ---------------------------------------------------------------------------
__device__ __forceinline__ uint32_t to_tf32(float x) {
    uint32_t y; asm("cvt.rna.tf32.f32 %0, %1;" : "=r"(y) : "f"(x)); return y;
}
__device__ __forceinline__ void mma_tf32(float* c, const uint32_t* a, const uint32_t* b) {
    asm volatile(
        "mma.sync.aligned.m16n8k8.row.col.f32.tf32.tf32.f32 "
        "{%0,%1,%2,%3}, {%4,%5,%6,%7}, {%8,%9}, {%0,%1,%2,%3};"
        : "+f"(c[0]), "+f"(c[1]), "+f"(c[2]), "+f"(c[3])
        : "r"(a[0]), "r"(a[1]), "r"(a[2]), "r"(a[3]), "r"(b[0]), "r"(b[1]));
}

// ---------------------------------------------------------------------------
// Weight transpose: WT[n][k] = W[k][n], 4 matrices of 1024x1024
// ---------------------------------------------------------------------------
__global__ __launch_bounds__(256) void transpose_w_kernel(
    const float* __restrict__ Wq, const float* __restrict__ Wk,
    const float* __restrict__ Wv, const float* __restrict__ Wo)
{
    __shared__ float t[32][33];
    const int z = blockIdx.z;
    const float* W = (z == 0) ? Wq : ((z == 1) ? Wk : ((z == 2) ? Wv : Wo));
    float* WT = g_scratch + 4ull * QKV_ELEMS + (size_t)z * WT_ELEMS;
    const int x0 = blockIdx.x * 32, y0 = blockIdx.y * 32;
    const int tx = threadIdx.x, ty = threadIdx.y;
#pragma unroll
    for (int j = 0; j < 32; j += 8)
        t[ty + j][tx] = W[(size_t)(y0 + ty + j) * Dd + x0 + tx];
    __syncthreads();
#pragma unroll
    for (int j = 0; j < 32; j += 8)
        WT[(size_t)(x0 + ty + j) * Dd + y0 + tx] = t[tx][ty + j];
}

// ---------------------------------------------------------------------------
// tf32 mma.sync GEMM: C[4096,1024] = A[4096,1024] @ W + bias  (BT = W^T)
// 128x128 CTA tile, BK=16, 8 warps (2x4), warp tile 64x32.
// Smem stride 20 floats: conflict-free STS and fragment LDS.
// ---------------------------------------------------------------------------
#define KST 20              // smem row stride in floats
#define TILE_F (128 * KST)  // floats per tile buffer

template<int SPLIT>
__device__ __forceinline__ void gemm_mma(const float* __restrict__ A,
                                         const float* __restrict__ BT,
                                         const float* __restrict__ bias,
                                         float* __restrict__ C)
{
    __shared__ uint32_t sm[2][2][TILE_F];   // [buf][a/b][...]

    const int tid = threadIdx.x;
    const int wid = tid >> 5, lane = tid & 31;
    const int m0 = blockIdx.y * 128, n0 = blockIdx.x * 128;

    // loader mapping: rlo = tid&7, c4 = (tid>>3)&3, rhi = tid>>5
    const int rlo = tid & 7;
    const int c4  = (tid >> 3) & 3;
    const int rhi = tid >> 5;
    const int r0 = rhi * 16 + rlo;          // first row
    const int r1 = r0 + 8;                  // second row
    const float* Ap0 = A  + (size_t)(m0 + r0) * Dd + c4 * 4;
    const float* Ap1 = A  + (size_t)(m0 + r1) * Dd + c4 * 4;
    const float* Bp0 = BT + (size_t)(n0 + r0) * Dd + c4 * 4;
    const float* Bp1 = BT + (size_t)(n0 + r1) * Dd + c4 * 4;
    const int so0 = r0 * KST + c4 * 4;
    const int so1 = r1 * KST + c4 * 4;

    // compute mapping
    const int wm = wid >> 2, wn = wid & 3;
    const int mbw = wm * 64, nbw = wn * 32;
    const int gr = lane >> 2, ck = lane & 3;

    float acc[4][4][4];
#pragma unroll
    for (int i = 0; i < 4; i++)
#pragma unroll
        for (int j = 0; j < 4; j++)
#pragma unroll
            for (int r = 0; r < 4; r++) acc[i][j][r] = 0.f;

    float4 pa0, pa1, pb0, pb1;
    // prologue: tile 0
    pa0 = *(const float4*)(Ap0); pa1 = *(const float4*)(Ap1);
    pb0 = *(const float4*)(Bp0); pb1 = *(const float4*)(Bp1);
    {
        uint32_t* da = sm[0][0]; uint32_t* db = sm[0][1];
        da[so0+0]=to_tf32(pa0.x); da[so0+1]=to_tf32(pa0.y); da[so0+2]=to_tf32(pa0.z); da[so0+3]=to_tf32(pa0.w);
        da[so1+0]=to_tf32(pa1.x); da[so1+1]=to_tf32(pa1.y); da[so1+2]=to_tf32(pa1.z); da[so1+3]=to_tf32(pa1.w);
        db[so0+0]=to_tf32(pb0.x); db[so0+1]=to_tf32(pb0.y); db[so0+2]=to_tf32(pb0.z); db[so0+3]=to_tf32(pb0.w);
        db[so1+0]=to_tf32(pb1.x); db[so1+1]=to_tf32(pb1.y); db[so1+2]=to_tf32(pb1.z); db[so1+3]=to_tf32(pb1.w);
    }
    __syncthreads();

    const int NIT = Dd / 16;   // 64
    for (int it = 0; it < NIT; ++it) {
        if (it + 1 < NIT) {
            const int k0 = (it + 1) * 16;
            pa0 = *(const float4*)(Ap0 + k0); pa1 = *(const float4*)(Ap1 + k0);
            pb0 = *(const float4*)(Bp0 + k0); pb1 = *(const float4*)(Bp1 + k0);
        }
        // compute from buffer it&1
        {
            const uint32_t* SA = sm[it & 1][0];
            const uint32_t* SB = sm[it & 1][1];
#pragma unroll
            for (int ks = 0; ks < 2; ks++) {
                const int kof = ks * 8;
                uint32_t bf[4][2];
#pragma unroll
                for (int nt = 0; nt < 4; nt++) {
                    const int nb = (nbw + nt * 8 + gr) * KST + kof + ck;
                    bf[nt][0] = SB[nb];
                    bf[nt][1] = SB[nb + 4];
                }
#pragma unroll
                for (int mt = 0; mt < 4; mt++) {
                    const int ab = (mbw + mt * 16 + gr) * KST + kof + ck;
                    uint32_t af[4];
                    af[0] = SA[ab];
                    af[1] = SA[ab + 8 * KST];
                    af[2] = SA[ab + 4];
                    af[3] = SA[ab + 8 * KST + 4];
#pragma unroll
                    for (int nt = 0; nt < 4; nt++)
                        mma_tf32(acc[mt][nt], af, bf[nt]);
                }
            }
        }
        if (it + 1 < NIT) {
            uint32_t* da = sm[(it + 1) & 1][0];
            uint32_t* db = sm[(it + 1) & 1][1];
            da[so0+0]=to_tf32(pa0.x); da[so0+1]=to_tf32(pa0.y); da[so0+2]=to_tf32(pa0.z); da[so0+3]=to_tf32(pa0.w);
            da[so1+0]=to_tf32(pa1.x); da[so1+1]=to_tf32(pa1.y); da[so1+2]=to_tf32(pa1.z); da[so1+3]=to_tf32(pa1.w);
            db[so0+0]=to_tf32(pb0.x); db[so0+1]=to_tf32(pb0.y); db[so0+2]=to_tf32(pb0.z); db[so0+3]=to_tf32(pb0.w);
            db[so1+0]=to_tf32(pb1.x); db[so1+1]=to_tf32(pb1.y); db[so1+2]=to_tf32(pb1.z); db[so1+3]=to_tf32(pb1.w);
            __syncthreads();
        }
    }

    // epilogue: write out with bias
#pragma unroll
    for (int mt = 0; mt < 4; mt++) {
        const int row = m0 + mbw + mt * 16 + gr;
#pragma unroll
        for (int nt = 0; nt < 4; nt++) {
            const int col = n0 + nbw + nt * 8 + 2 * ck;
            const float2 bi = *(const float2*)(bias + col);
            float2 v0, v1;
            v0.x = acc[mt][nt][0] + bi.x; v0.y = acc[mt][nt][1] + bi.y;
            v1.x = acc[mt][nt][2] + bi.x; v1.y = acc[mt][nt][3] + bi.y;
            if (SPLIT) {
                const int h = col >> 6, d = col & 63;
                const int b0_ = row >> 11, s0 = row & 2047;
                *(float2*)&C[(((size_t)(b0_ * Hh + h)) * Ss + s0) * HDd + d] = v0;
                const int row1 = row + 8;
                const int b1_ = row1 >> 11, s1 = row1 & 2047;
                *(float2*)&C[(((size_t)(b1_ * Hh + h)) * Ss + s1) * HDd + d] = v1;
            } else {
                *(float2*)&C[(size_t)row * Dd + col] = v0;
                *(float2*)&C[(size_t)(row + 8) * Dd + col] = v1;
            }
        }
    }
}

__global__ __launch_bounds__(256) void gemm_qkv_mma_kernel(
    const float* __restrict__ Aq, const float* __restrict__ Ak, const float* __restrict__ Av,
    const float* __restrict__ bq, const float* __restrict__ bk, const float* __restrict__ bv)
{
    const int z = blockIdx.z;
    const float* A    = (z == 0) ? Aq : ((z == 1) ? Ak : Av);
    const float* bias = (z == 0) ? bq : ((z == 1) ? bk : bv);
    const float* BT = g_scratch + 4ull * QKV_ELEMS + (size_t)z * WT_ELEMS;
    float* C = g_scratch + (size_t)z * QKV_ELEMS;
    gemm_mma<1>(A, BT, bias, C);
}

__global__ __launch_bounds__(256) void gemm_out_mma_kernel(
    const float* __restrict__ bo, float* __restrict__ out)
{
    const float* A  = g_scratch + 3ull * QKV_ELEMS;                    // concat
    const float* BT = g_scratch + 4ull * QKV_ELEMS + 3ull * WT_ELEMS;  // WoT
    gemm_mma<0>(A, BT, bo, out);
}

// ---------------------------------------------------------------------------
// Flash attention, causal, fp32 (unchanged)
// ---------------------------------------------------------------------------
#define BQ 128
#define BK 16

__global__ __launch_bounds__(128) void attn_kernel()
{
    const int bh  = blockIdx.y;
    const int q0  = blockIdx.x * BQ;
    const int tid = threadIdx.x;
    const int q   = q0 + tid;

    const float* Qp = g_scratch + (size_t)bh * (Ss * HDd);
    const float* Kp = g_scratch + (size_t)QKV_ELEMS     + (size_t)bh * (Ss * HDd);
    const float* Vp = g_scratch + (size_t)2 * QKV_ELEMS + (size_t)bh * (Ss * HDd);

    __shared__ float sK[BK * HDd];
    __shared__ float sV[BK * HDd];

    float qreg[HDd];
#pragma unroll
    for (int d = 0; d < HDd; d += 4)
        *(float4*)&qreg[d] = *(const float4*)&Qp[(size_t)q * HDd + d];

    const float scale = 0.125f;
    float m = -1e30f, l = 0.f;
    float o[HDd];
#pragma unroll
    for (int d = 0; d < HDd; d++) o[d] = 0.f;

    const int kmax = q0 + BQ;
    const int base = tid * 8;

    for (int t0 = 0; t0 < kmax; t0 += BK) {
        const size_t gbase = (size_t)t0 * HDd + base;
        *(float4*)(sK + base)     = *(const float4*)(Kp + gbase);
        *(float4*)(sK + base + 4) = *(const float4*)(Kp + gbase + 4);
        *(float4*)(sV + base)     = *(const float4*)(Vp + gbase);
        *(float4*)(sV + base + 4) = *(const float4*)(Vp + gbase + 4);
        __syncthreads();

        if (t0 <= q) {
            float s[BK];
            float mt = -1e30f;
#pragma unroll
            for (int j = 0; j < BK; j++) {
                float acc = 0.f;
                const float* kr = sK + j * HDd;
#pragma unroll
                for (int d = 0; d < HDd; d += 4) {
                    float4 k4 = *(const float4*)(kr + d);
                    acc = fmaf(qreg[d],     k4.x, acc);
                    acc = fmaf(qreg[d + 1], k4.y, acc);
                    acc = fmaf(qreg[d + 2], k4.z, acc);
                    acc = fmaf(qreg[d + 3], k4.w, acc);
                }
                s[j] = (t0 + j <= q) ? acc * scale : -1e30f;
                mt = fmaxf(mt, s[j]);
            }
            float mnew = fmaxf(m, mt);
            float corr = __expf(m - mnew);
            l *= corr;
#pragma unroll
            for (int d = 0; d < HDd; d++) o[d] *= corr;
#pragma unroll
            for (int j = 0; j < BK; j++) {
                float p = __expf(s[j] - mnew);
                l += p;
                const float* vr = sV + j * HDd;
#pragma unroll
                for (int d = 0; d < HDd; d += 4) {
                    float4 v4 = *(const float4*)(vr + d);
                    o[d]     = fmaf(p, v4.x, o[d]);
                    o[d + 1] = fmaf(p, v4.y, o[d + 1]);
                    o[d + 2] = fmaf(p, v4.z, o[d + 2]);
                    o[d + 3] = fmaf(p, v4.w, o[d + 3]);
                }
            }
            m = mnew;
        }
        __syncthreads();
    }

    const float inv = 1.f / l;
    const int bb = bh >> 4;
    const int h  = bh & 15;
    float* outp = g_scratch + 3ull * QKV_ELEMS
                + ((size_t)(bb * Ss + q)) * Dd + h * HDd;
#pragma unroll
    for (int d = 0; d < HDd; d += 4) {
        float4 r;
        r.x = o[d] * inv; r.y = o[d + 1] * inv;
        r.z = o[d + 2] * inv; r.w = o[d + 3] * inv;
        *(float4*)(outp + d) = r;
    }
}

// ---------------------------------------------------------------------------
extern "C" void kernel_launch(void* const* d_in, const int* in_sizes, int n_in,
                              void* d_out, int out_size)
{
    const float* q_in = (const float*)d_in[0];
    const float* k_in = (const float*)d_in[1];
    const float* v_in = (const float*)d_in[2];
    const float* Wq   = (const float*)d_in[3];
    const float* bq   = (const float*)d_in[4];
    const float* Wk   = (const float*)d_in[5];
    const float* bk   = (const float*)d_in[6];
    const float* Wv   = (const float*)d_in[7];
    const float* bv   = (const float*)d_in[8];
    const float* Wo   = (const float*)d_in[9];
    const float* bo   = (const float*)d_in[10];
    float* out = (float*)d_out;

    transpose_w_kernel<<<dim3(32, 32, 4), dim3(32, 8)>>>(Wq, Wk, Wv, Wo);

    gemm_qkv_mma_kernel<<<dim3(8, 32, 3), 256>>>(q_in, k_in, v_in, bq, bk, bv);

    attn_kernel<<<dim3(Ss / BQ, Bb * Hh), 128>>>();

    gemm_out_mma_kernel<<<dim3(8, 32), 256>>>(bo, out);
}

// round 4
// speedup vs baseline: 1.4044x; 1.2119x over previous
#include <cuda_runtime.h>
#include <cstdint>

#define Bb 2
#define Ss 2048
#define Dd 1024
#define Hh 16
#define HDd 64
#define QKV_ELEMS (Bb*Hh*Ss*HDd)   // 4194304
#define WT_ELEMS (Dd*Dd)           // 1048576

#define OFF_CAT (3ull*QKV_ELEMS)
#define OFF_WT  (4ull*QKV_ELEMS)
#define OFF_AR  (4ull*QKV_ELEMS + 4ull*WT_ELEMS)

// q,k,v,concat, WT x4, rounded inputs x3
static __device__ float g_scratch[7ull*QKV_ELEMS + 4ull*WT_ELEMS];

// ---------------------------------------------------------------------------
__device__ __forceinline__ uint32_t smem_u32(const void* p) {
    uint32_t a;
    asm("{ .reg .u64 t; cvta.to.shared.u64 t, %1; cvt.u32.u64 %0, t; }"
        : "=r"(a) : "l"(p));
    return a;
}
__device__ __forceinline__ float to_tf32f(float x) {
    uint32_t y; asm("cvt.rna.tf32.f32 %0, %1;" : "=r"(y) : "f"(x));
    return __uint_as_float(y);
}
__device__ __forceinline__ void mma_tf32(float* c, const uint32_t* a, const uint32_t* b) {
    asm volatile(
        "mma.sync.aligned.m16n8k8.row.col.f32.tf32.tf32.f32 "
        "{%0,%1,%2,%3}, {%4,%5,%6,%7}, {%8,%9}, {%0,%1,%2,%3};"
        : "+f"(c[0]), "+f"(c[1]), "+f"(c[2]), "+f"(c[3])
        : "r"(a[0]), "r"(a[1]), "r"(a[2]), "r"(a[3]), "r"(b[0]), "r"(b[1]));
}
#define CP16(smem_addr, gptr) \
    asm volatile("cp.async.ca.shared.global [%0], [%1], 16;" \
                 :: "r"(smem_addr), "l"(gptr) : "memory")
#define CPCOMMIT() asm volatile("cp.async.commit_group;" ::: "memory")
#define CPWAIT(N)  asm volatile("cp.async.wait_group %0;" :: "n"(N) : "memory")

// ---------------------------------------------------------------------------
// Prep: round activations to tf32 (stored as fp32 bit patterns)
// ---------------------------------------------------------------------------
__global__ __launch_bounds__(256) void round_inputs_kernel(
    const float* __restrict__ q, const float* __restrict__ k,
    const float* __restrict__ v)
{
    const int z = blockIdx.y;
    const float* in = (z == 0) ? q : ((z == 1) ? k : v);
    float* out = g_scratch + OFF_AR + (size_t)z * QKV_ELEMS;
    const size_t i = ((size_t)blockIdx.x * 256 + threadIdx.x) * 4;
    float4 t = *(const float4*)(in + i);
    t.x = to_tf32f(t.x); t.y = to_tf32f(t.y);
    t.z = to_tf32f(t.z); t.w = to_tf32f(t.w);
    *(float4*)(out + i) = t;
}

// Weight transpose + round: WT[n][k] = tf32(W[k][n])
__global__ __launch_bounds__(256) void transpose_w_kernel(
    const float* __restrict__ Wq, const float* __restrict__ Wk,
    const float* __restrict__ Wv, const float* __restrict__ Wo)
{
    __shared__ float t[32][33];
    const int z = blockIdx.z;
    const float* W = (z == 0) ? Wq : ((z == 1) ? Wk : ((z == 2) ? Wv : Wo));
    float* WT = g_scratch + OFF_WT + (size_t)z * WT_ELEMS;
    const int x0 = blockIdx.x * 32, y0 = blockIdx.y * 32;
    const int tx = threadIdx.x, ty = threadIdx.y;
#pragma unroll
    for (int j = 0; j < 32; j += 8)
        t[ty + j][tx] = W[(size_t)(y0 + ty + j) * Dd + x0 + tx];
    __syncthreads();
#pragma unroll
    for (int j = 0; j < 32; j += 8)
        WT[(size_t)(x0 + ty + j) * Dd + y0 + tx] = to_tf32f(t[tx][ty + j]);
}

// ---------------------------------------------------------------------------
// tf32 mma.sync GEMM with 4-stage cp.async pipeline.
// A, BT already tf32-rounded. 128x128 CTA tile, BK=16, 8 warps (2x4).
// ---------------------------------------------------------------------------
#define KST 20
#define TILE_F (128 * KST)        // 2560 floats
#define STAGE_F (2 * TILE_F)      // 5120 floats
#define NSTAGE 4
#define GEMM_SMEM_BYTES (NSTAGE * STAGE_F * 4)   // 81920

template<int SPLIT>
__device__ __forceinline__ void gemm_mma(const float* __restrict__ A,
                                         const float* __restrict__ BT,
                                         const float* __restrict__ bias,
                                         float* __restrict__ C)
{
    extern __shared__ float smf[];

    const int tid = threadIdx.x;
    const int wid = tid >> 5, lane = tid & 31;
    const int m0 = blockIdx.y * 128, n0 = blockIdx.x * 128;

    // loader: thread -> two rows (row0, row0+64), 4-float chunk c4
    const int row0 = tid >> 2, c4 = tid & 3;
    const uint32_t so0 = row0 * 80 + c4 * 16;          // bytes
    const uint32_t so1 = (row0 + 64) * 80 + c4 * 16;
    const float* gA0 = A  + (size_t)(m0 + row0) * Dd + c4 * 4;
    const float* gA1 = A  + (size_t)(m0 + row0 + 64) * Dd + c4 * 4;
    const float* gB0 = BT + (size_t)(n0 + row0) * Dd + c4 * 4;
    const float* gB1 = BT + (size_t)(n0 + row0 + 64) * Dd + c4 * 4;
    const uint32_t sbase = smem_u32(smf);

    // compute mapping
    const int wm = wid >> 2, wn = wid & 3;
    const int mbw = wm * 64, nbw = wn * 32;
    const int gr = lane >> 2, ck = lane & 3;

    float acc[4][4][4];
#pragma unroll
    for (int i = 0; i < 4; i++)
#pragma unroll
        for (int j = 0; j < 4; j++)
#pragma unroll
            for (int r = 0; r < 4; r++) acc[i][j][r] = 0.f;

#define GISSUE(buf, k0) do { \
        uint32_t a_ = sbase + (uint32_t)(buf) * (STAGE_F * 4); \
        uint32_t b_ = a_ + TILE_F * 4; \
        CP16(a_ + so0, gA0 + (k0)); CP16(a_ + so1, gA1 + (k0)); \
        CP16(b_ + so0, gB0 + (k0)); CP16(b_ + so1, gB1 + (k0)); \
        CPCOMMIT(); \
    } while (0)

    GISSUE(0, 0); GISSUE(1, 16); GISSUE(2, 32);

    const int NIT = Dd / 16;   // 64
    for (int it = 0; it < NIT; ++it) {
        CPWAIT(2);
        __syncthreads();
        if (it + 3 < NIT) GISSUE((it + 3) & 3, (it + 3) * 16);

        const uint32_t* SA = (const uint32_t*)(smf + (size_t)(it & 3) * STAGE_F);
        const uint32_t* SB = SA + TILE_F;
#pragma unroll
        for (int ks = 0; ks < 2; ks++) {
            const int kof = ks * 8;
            uint32_t bf[4][2];
#pragma unroll
            for (int nt = 0; nt < 4; nt++) {
                const int nb = (nbw + nt * 8 + gr) * KST + kof + ck;
                bf[nt][0] = SB[nb];
                bf[nt][1] = SB[nb + 4];
            }
#pragma unroll
            for (int mt = 0; mt < 4; mt++) {
                const int ab = (mbw + mt * 16 + gr) * KST + kof + ck;
                uint32_t af[4];
                af[0] = SA[ab];
                af[1] = SA[ab + 8 * KST];
                af[2] = SA[ab + 4];
                af[3] = SA[ab + 8 * KST + 4];
#pragma unroll
                for (int nt = 0; nt < 4; nt++)
                    mma_tf32(acc[mt][nt], af, bf[nt]);
            }
        }
    }
#undef GISSUE

    // epilogue with bias
#pragma unroll
    for (int mt = 0; mt < 4; mt++) {
        const int row = m0 + mbw + mt * 16 + gr;
#pragma unroll
        for (int nt = 0; nt < 4; nt++) {
            const int col = n0 + nbw + nt * 8 + 2 * ck;
            const float2 bi = *(const float2*)(bias + col);
            float2 v0, v1;
            v0.x = acc[mt][nt][0] + bi.x; v0.y = acc[mt][nt][1] + bi.y;
            v1.x = acc[mt][nt][2] + bi.x; v1.y = acc[mt][nt][3] + bi.y;
            if (SPLIT) {
                const int h = col >> 6, d = col & 63;
                const int b0_ = row >> 11, s0 = row & 2047;
                *(float2*)&C[(((size_t)(b0_ * Hh + h)) * Ss + s0) * HDd + d] = v0;
                const int row1 = row + 8;
                const int b1_ = row1 >> 11, s1 = row1 & 2047;
                *(float2*)&C[(((size_t)(b1_ * Hh + h)) * Ss + s1) * HDd + d] = v1;
            } else {
                *(float2*)&C[(size_t)row * Dd + col] = v0;
                *(float2*)&C[(size_t)(row + 8) * Dd + col] = v1;
            }
        }
    }
}

__global__ __launch_bounds__(256, 2) void gemm_qkv_mma_kernel(
    const float* __restrict__ bq, const float* __restrict__ bk,
    const float* __restrict__ bv)
{
    const int z = blockIdx.z;
    const float* A    = g_scratch + OFF_AR + (size_t)z * QKV_ELEMS;
    const float* bias = (z == 0) ? bq : ((z == 1) ? bk : bv);
    const float* BT   = g_scratch + OFF_WT + (size_t)z * WT_ELEMS;
    float* C = g_scratch + (size_t)z * QKV_ELEMS;
    gemm_mma<1>(A, BT, bias, C);
}

__global__ __launch_bounds__(256, 2) void gemm_out_mma_kernel(
    const float* __restrict__ bo, float* __restrict__ out)
{
    const float* A  = g_scratch + OFF_CAT;                 // concat (pre-rounded)
    const float* BT = g_scratch + OFF_WT + 3ull * WT_ELEMS;
    gemm_mma<0>(A, BT, bo, out);
}

// ---------------------------------------------------------------------------
// Flash attention, causal, fp32. cp.async double-buffered K/V tiles,
// 4-way interleaved QK accumulator chains, 1 barrier per 16-key tile.
// ---------------------------------------------------------------------------
#define BQ 128
#define BK 16

__global__ __launch_bounds__(128, 3) void attn_kernel()
{
    __shared__ float sKV[2][2][BK * HDd];   // [buf][K/V][...]

    const int bh  = blockIdx.y;
    const int q0  = blockIdx.x * BQ;
    const int tid = threadIdx.x;
    const int q   = q0 + tid;

    const float* Qp = g_scratch + (size_t)bh * (Ss * HDd);
    const float* Kp = g_scratch + (size_t)QKV_ELEMS     + (size_t)bh * (Ss * HDd);
    const float* Vp = g_scratch + (size_t)2 * QKV_ELEMS + (size_t)bh * (Ss * HDd);

    const int i0 = tid, i1 = tid + 128;   // float4 indices (256 per tile)

#define AISSUE(buf, t0) do { \
        const float* kg = Kp + (size_t)(t0) * HDd; \
        const float* vg = Vp + (size_t)(t0) * HDd; \
        uint32_t sk = smem_u32(sKV[buf][0]); \
        uint32_t sv = smem_u32(sKV[buf][1]); \
        CP16(sk + i0 * 16, kg + i0 * 4); CP16(sk + i1 * 16, kg + i1 * 4); \
        CP16(sv + i0 * 16, vg + i0 * 4); CP16(sv + i1 * 16, vg + i1 * 4); \
        CPCOMMIT(); \
    } while (0)

    AISSUE(0, 0);

    float qreg[HDd];
#pragma unroll
    for (int d = 0; d < HDd; d += 4)
        *(float4*)&qreg[d] = *(const float4*)&Qp[(size_t)q * HDd + d];

    const float scale = 0.125f;
    float m = -1e30f, l = 0.f;
    float o[HDd];
#pragma unroll
    for (int d = 0; d < HDd; d++) o[d] = 0.f;

    const int ntiles = (q0 + BQ) / BK;

    for (int i = 0; i < ntiles; i++) {
        CPWAIT(0);
        __syncthreads();
        if (i + 1 < ntiles) AISSUE((i + 1) & 1, (i + 1) * BK);

        const int t0 = i * BK;
        if (t0 <= q) {
            const float* sK = sKV[i & 1][0];
            const float* sV = sKV[i & 1][1];
            float s[BK];
            float mt = -1e30f;
#pragma unroll
            for (int j0 = 0; j0 < BK; j0 += 4) {
                float a0 = 0.f, a1 = 0.f, a2 = 0.f, a3 = 0.f;
                const float* k0r = sK + (j0 + 0) * HDd;
                const float* k1r = sK + (j0 + 1) * HDd;
                const float* k2r = sK + (j0 + 2) * HDd;
                const float* k3r = sK + (j0 + 3) * HDd;
#pragma unroll
                for (int d = 0; d < HDd; d += 4) {
                    float4 x0 = *(const float4*)(k0r + d);
                    float4 x1 = *(const float4*)(k1r + d);
                    float4 x2 = *(const float4*)(k2r + d);
                    float4 x3 = *(const float4*)(k3r + d);
                    a0 = fmaf(qreg[d], x0.x, a0); a1 = fmaf(qreg[d], x1.x, a1);
                    a2 = fmaf(qreg[d], x2.x, a2); a3 = fmaf(qreg[d], x3.x, a3);
                    a0 = fmaf(qreg[d+1], x0.y, a0); a1 = fmaf(qreg[d+1], x1.y, a1);
                    a2 = fmaf(qreg[d+1], x2.y, a2); a3 = fmaf(qreg[d+1], x3.y, a3);
                    a0 = fmaf(qreg[d+2], x0.z, a0); a1 = fmaf(qreg[d+2], x1.z, a1);
                    a2 = fmaf(qreg[d+2], x2.z, a2); a3 = fmaf(qreg[d+2], x3.z, a3);
                    a0 = fmaf(qreg[d+3], x0.w, a0); a1 = fmaf(qreg[d+3], x1.w, a1);
                    a2 = fmaf(qreg[d+3], x2.w, a2); a3 = fmaf(qreg[d+3], x3.w, a3);
                }
                s[j0 + 0] = (t0 + j0 + 0 <= q) ? a0 * scale : -1e30f;
                s[j0 + 1] = (t0 + j0 + 1 <= q) ? a1 * scale : -1e30f;
                s[j0 + 2] = (t0 + j0 + 2 <= q) ? a2 * scale : -1e30f;
                s[j0 + 3] = (t0 + j0 + 3 <= q) ? a3 * scale : -1e30f;
                mt = fmaxf(mt, fmaxf(fmaxf(s[j0], s[j0+1]), fmaxf(s[j0+2], s[j0+3])));
            }
            float mnew = fmaxf(m, mt);
            float corr = __expf(m - mnew);
            l *= corr;
#pragma unroll
            for (int d = 0; d < HDd; d++) o[d] *= corr;
#pragma unroll
            for (int j = 0; j < BK; j++) {
                float p = __expf(s[j] - mnew);
                l += p;
                const float* vr = sV + j * HDd;
#pragma unroll
                for (int d = 0; d < HDd; d += 4) {
                    float4 v4 = *(const float4*)(vr + d);
                    o[d]     = fmaf(p, v4.x, o[d]);
                    o[d + 1] = fmaf(p, v4.y, o[d + 1]);
                    o[d + 2] = fmaf(p, v4.z, o[d + 2]);
                    o[d + 3] = fmaf(p, v4.w, o[d + 3]);
                }
            }
            m = mnew;
        }
    }
#undef AISSUE

    const float inv = 1.f / l;
    const int bb = bh >> 4;
    const int h  = bh & 15;
    float* outp = g_scratch + OFF_CAT
                + ((size_t)(bb * Ss + q)) * Dd + h * HDd;
#pragma unroll
    for (int d = 0; d < HDd; d += 4) {
        float4 r;
        r.x = to_tf32f(o[d] * inv);     r.y = to_tf32f(o[d + 1] * inv);
        r.z = to_tf32f(o[d + 2] * inv); r.w = to_tf32f(o[d + 3] * inv);
        *(float4*)(outp + d) = r;
    }
}

// ---------------------------------------------------------------------------
extern "C" void kernel_launch(void* const* d_in, const int* in_sizes, int n_in,
                              void* d_out, int out_size)
{
    const float* q_in = (const float*)d_in[0];
    const float* k_in = (const float*)d_in[1];
    const float* v_in = (const float*)d_in[2];
    const float* bq   = (const float*)d_in[4];
    const float* bk   = (const float*)d_in[6];
    const float* bv   = (const float*)d_in[8];
    const float* Wq   = (const float*)d_in[3];
    const float* Wk   = (const float*)d_in[5];
    const float* Wv   = (const float*)d_in[7];
    const float* Wo   = (const float*)d_in[9];
    const float* bo   = (const float*)d_in[10];
    float* out = (float*)d_out;

    cudaFuncSetAttribute(gemm_qkv_mma_kernel,
                         cudaFuncAttributeMaxDynamicSharedMemorySize, GEMM_SMEM_BYTES);
    cudaFuncSetAttribute(gemm_out_mma_kernel,
                         cudaFuncAttributeMaxDynamicSharedMemorySize, GEMM_SMEM_BYTES);

    round_inputs_kernel<<<dim3(QKV_ELEMS / 1024, 3), 256>>>(q_in, k_in, v_in);
    transpose_w_kernel<<<dim3(32, 32, 4), dim3(32, 8)>>>(Wq, Wk, Wv, Wo);

    gemm_qkv_mma_kernel<<<dim3(8, 32, 3), 256, GEMM_SMEM_BYTES>>>(bq, bk, bv);

    attn_kernel<<<dim3(Ss / BQ, Bb * Hh), 128>>>();

    gemm_out_mma_kernel<<<dim3(8, 32), 256, GEMM_SMEM_BYTES>>>(bo, out);
}

// round 5
// speedup vs baseline: 3.4857x; 2.4819x over previous
#include <cuda_runtime.h>
#include <cstdint>

#define Bb 2
#define Ss 2048
#define Dd 1024
#define Hh 16
#define HDd 64
#define QKV_ELEMS (Bb*Hh*Ss*HDd)   // 4194304
#define WT_ELEMS (Dd*Dd)           // 1048576

#define OFF_CAT (3ull*QKV_ELEMS)
#define OFF_WT  (4ull*QKV_ELEMS)
#define OFF_AR  (4ull*QKV_ELEMS + 4ull*WT_ELEMS)

// q,k,v,concat, WT x4, rounded inputs x3
static __device__ float g_scratch[7ull*QKV_ELEMS + 4ull*WT_ELEMS];

// ---------------------------------------------------------------------------
__device__ __forceinline__ uint32_t smem_u32(const void* p) {
    uint32_t a;
    asm("{ .reg .u64 t; cvta.to.shared.u64 t, %1; cvt.u32.u64 %0, t; }"
        : "=r"(a) : "l"(p));
    return a;
}
__device__ __forceinline__ float to_tf32f(float x) {
    uint32_t y; asm("cvt.rna.tf32.f32 %0, %1;" : "=r"(y) : "f"(x));
    return __uint_as_float(y);
}
__device__ __forceinline__ void mma_tf32(float* c, const uint32_t* a, const uint32_t* b) {
    asm volatile(
        "mma.sync.aligned.m16n8k8.row.col.f32.tf32.tf32.f32 "
        "{%0,%1,%2,%3}, {%4,%5,%6,%7}, {%8,%9}, {%0,%1,%2,%3};"
        : "+f"(c[0]), "+f"(c[1]), "+f"(c[2]), "+f"(c[3])
        : "r"(a[0]), "r"(a[1]), "r"(a[2]), "r"(a[3]), "r"(b[0]), "r"(b[1]));
}
#define CP16(smem_addr, gptr) \
    asm volatile("cp.async.ca.shared.global [%0], [%1], 16;" \
                 :: "r"(smem_addr), "l"(gptr) : "memory")
#define CPCOMMIT() asm volatile("cp.async.commit_group;" ::: "memory")
#define CPWAIT(N)  asm volatile("cp.async.wait_group %0;" :: "n"(N) : "memory")

// ---------------------------------------------------------------------------
// Prep: round activations to tf32 (stored as fp32 bit patterns)
// ---------------------------------------------------------------------------
__global__ __launch_bounds__(256) void round_inputs_kernel(
    const float* __restrict__ q, const float* __restrict__ k,
    const float* __restrict__ v)
{
    const int z = blockIdx.y;
    const float* in = (z == 0) ? q : ((z == 1) ? k : v);
    float* out = g_scratch + OFF_AR + (size_t)z * QKV_ELEMS;
    const size_t i = ((size_t)blockIdx.x * 256 + threadIdx.x) * 4;
    float4 t = *(const float4*)(in + i);
    t.x = to_tf32f(t.x); t.y = to_tf32f(t.y);
    t.z = to_tf32f(t.z); t.w = to_tf32f(t.w);
    *(float4*)(out + i) = t;
}

// Weight transpose + round: WT[n][k] = tf32(W[k][n])
__global__ __launch_bounds__(256) void transpose_w_kernel(
    const float* __restrict__ Wq, const float* __restrict__ Wk,
    const float* __restrict__ Wv, const float* __restrict__ Wo)
{
    __shared__ float t[32][33];
    const int z = blockIdx.z;
    const float* W = (z == 0) ? Wq : ((z == 1) ? Wk : ((z == 2) ? Wv : Wo));
    float* WT = g_scratch + OFF_WT + (size_t)z * WT_ELEMS;
    const int x0 = blockIdx.x * 32, y0 = blockIdx.y * 32;
    const int tx = threadIdx.x, ty = threadIdx.y;
#pragma unroll
    for (int j = 0; j < 32; j += 8)
        t[ty + j][tx] = W[(size_t)(y0 + ty + j) * Dd + x0 + tx];
    __syncthreads();
#pragma unroll
    for (int j = 0; j < 32; j += 8)
        WT[(size_t)(x0 + ty + j) * Dd + y0 + tx] = to_tf32f(t[tx][ty + j]);
}

// ---------------------------------------------------------------------------
// tf32 mma.sync GEMM with 4-stage cp.async pipeline.
// A, BT already tf32-rounded. 128x128 CTA tile, BK=16, 8 warps (2x4).
// SPLIT=1 also tf32-rounds the stored outputs (consumed by mma attention).
// ---------------------------------------------------------------------------
#define KST 20
#define TILE_F (128 * KST)        // 2560 floats
#define STAGE_F (2 * TILE_F)      // 5120 floats
#define NSTAGE 4
#define GEMM_SMEM_BYTES (NSTAGE * STAGE_F * 4)   // 81920

template<int SPLIT>
__device__ __forceinline__ void gemm_mma(const float* __restrict__ A,
                                         const float* __restrict__ BT,
                                         const float* __restrict__ bias,
                                         float* __restrict__ C)
{
    extern __shared__ float smf[];

    const int tid = threadIdx.x;
    const int wid = tid >> 5, lane = tid & 31;
    const int m0 = blockIdx.y * 128, n0 = blockIdx.x * 128;

    const int row0 = tid >> 2, c4 = tid & 3;
    const uint32_t so0 = row0 * 80 + c4 * 16;          // bytes
    const uint32_t so1 = (row0 + 64) * 80 + c4 * 16;
    const float* gA0 = A  + (size_t)(m0 + row0) * Dd + c4 * 4;
    const float* gA1 = A  + (size_t)(m0 + row0 + 64) * Dd + c4 * 4;
    const float* gB0 = BT + (size_t)(n0 + row0) * Dd + c4 * 4;
    const float* gB1 = BT + (size_t)(n0 + row0 + 64) * Dd + c4 * 4;
    const uint32_t sbase = smem_u32(smf);

    const int wm = wid >> 2, wn = wid & 3;
    const int mbw = wm * 64, nbw = wn * 32;
    const int gr = lane >> 2, ck = lane & 3;

    float acc[4][4][4];
#pragma unroll
    for (int i = 0; i < 4; i++)
#pragma unroll
        for (int j = 0; j < 4; j++)
#pragma unroll
            for (int r = 0; r < 4; r++) acc[i][j][r] = 0.f;

#define GISSUE(buf, k0) do { \
        uint32_t a_ = sbase + (uint32_t)(buf) * (STAGE_F * 4); \
        uint32_t b_ = a_ + TILE_F * 4; \
        CP16(a_ + so0, gA0 + (k0)); CP16(a_ + so1, gA1 + (k0)); \
        CP16(b_ + so0, gB0 + (k0)); CP16(b_ + so1, gB1 + (k0)); \
        CPCOMMIT(); \
    } while (0)

    GISSUE(0, 0); GISSUE(1, 16); GISSUE(2, 32);

    const int NIT = Dd / 16;   // 64
    for (int it = 0; it < NIT; ++it) {
        CPWAIT(2);
        __syncthreads();
        if (it + 3 < NIT) GISSUE((it + 3) & 3, (it + 3) * 16);

        const uint32_t* SA = (const uint32_t*)(smf + (size_t)(it & 3) * STAGE_F);
        const uint32_t* SB = SA + TILE_F;
#pragma unroll
        for (int ks = 0; ks < 2; ks++) {
            const int kof = ks * 8;
            uint32_t bf[4][2];
#pragma unroll
            for (int nt = 0; nt < 4; nt++) {
                const int nb = (nbw + nt * 8 + gr) * KST + kof + ck;
                bf[nt][0] = SB[nb];
                bf[nt][1] = SB[nb + 4];
            }
#pragma unroll
            for (int mt = 0; mt < 4; mt++) {
                const int ab = (mbw + mt * 16 + gr) * KST + kof + ck;
                uint32_t af[4];
                af[0] = SA[ab];
                af[1] = SA[ab + 8 * KST];
                af[2] = SA[ab + 4];
                af[3] = SA[ab + 8 * KST + 4];
#pragma unroll
                for (int nt = 0; nt < 4; nt++)
                    mma_tf32(acc[mt][nt], af, bf[nt]);
            }
        }
    }
#undef GISSUE

#pragma unroll
    for (int mt = 0; mt < 4; mt++) {
        const int row = m0 + mbw + mt * 16 + gr;
#pragma unroll
        for (int nt = 0; nt < 4; nt++) {
            const int col = n0 + nbw + nt * 8 + 2 * ck;
            const float2 bi = *(const float2*)(bias + col);
            float2 v0, v1;
            v0.x = acc[mt][nt][0] + bi.x; v0.y = acc[mt][nt][1] + bi.y;
            v1.x = acc[mt][nt][2] + bi.x; v1.y = acc[mt][nt][3] + bi.y;
            if (SPLIT) {
                // round for the tf32 mma attention consumer
                v0.x = to_tf32f(v0.x); v0.y = to_tf32f(v0.y);
                v1.x = to_tf32f(v1.x); v1.y = to_tf32f(v1.y);
                const int h = col >> 6, d = col & 63;
                const int b0_ = row >> 11, s0 = row & 2047;
                *(float2*)&C[(((size_t)(b0_ * Hh + h)) * Ss + s0) * HDd + d] = v0;
                const int row1 = row + 8;
                const int b1_ = row1 >> 11, s1 = row1 & 2047;
                *(float2*)&C[(((size_t)(b1_ * Hh + h)) * Ss + s1) * HDd + d] = v1;
            } else {
                *(float2*)&C[(size_t)row * Dd + col] = v0;
                *(float2*)&C[(size_t)(row + 8) * Dd + col] = v1;
            }
        }
    }
}

__global__ __launch_bounds__(256, 2) void gemm_qkv_mma_kernel(
    const float* __restrict__ bq, const float* __restrict__ bk,
    const float* __restrict__ bv)
{
    const int z = blockIdx.z;
    const float* A    = g_scratch + OFF_AR + (size_t)z * QKV_ELEMS;
    const float* bias = (z == 0) ? bq : ((z == 1) ? bk : bv);
    const float* BT   = g_scratch + OFF_WT + (size_t)z * WT_ELEMS;
    float* C = g_scratch + (size_t)z * QKV_ELEMS;
    gemm_mma<1>(A, BT, bias, C);
}

__global__ __launch_bounds__(256, 2) void gemm_out_mma_kernel(
    const float* __restrict__ bo, float* __restrict__ out)
{
    const float* A  = g_scratch + OFF_CAT;                 // concat (pre-rounded)
    const float* BT = g_scratch + OFF_WT + 3ull * WT_ELEMS;
    gemm_mma<0>(A, BT, bo, out);
}

// ---------------------------------------------------------------------------
// MMA flash attention (tf32), causal. CTA: 128 queries, 4 warps x 32 rows.
// K/V tiles of 32 keys, cp.async double-buffered. Online softmax in fragments.
// ---------------------------------------------------------------------------
#define AST 68                        // sQ/sK row stride (floats)
#define VST 72                        // sV row stride
#define SK_OFF (128*AST)              // 8704
#define SK_BUF (32*AST)               // 2176
#define SV_OFF (SK_OFF + 2*SK_BUF)    // 13056
#define SV_BUF (32*VST)               // 2304
#define ATTN_SMEM_BYTES ((SV_OFF + 2*SV_BUF) * 4)   // 70656

__global__ __launch_bounds__(128, 2) void attn_mma_kernel()
{
    extern __shared__ float sm[];
    const int bh = blockIdx.y;
    const int qt = 15 - blockIdx.x;        // longest CTAs launch first
    const int q0 = qt * 128;
    const int tid = threadIdx.x;
    const int wq = tid >> 5, lane = tid & 31;
    const int gr = lane >> 2, tg = lane & 3;

    const float* Qp = g_scratch + (size_t)bh * (Ss * HDd) + (size_t)q0 * HDd;
    const float* Kp = g_scratch + (size_t)QKV_ELEMS     + (size_t)bh * (Ss * HDd);
    const float* Vp = g_scratch + 2ull * QKV_ELEMS      + (size_t)bh * (Ss * HDd);

    const uint32_t smb = smem_u32(sm);

#define KISSUE(buf, t0) do { \
        _Pragma("unroll") \
        for (int j_ = 0; j_ < 4; j_++) { \
            const int f_ = tid + j_ * 128; \
            const int r_ = f_ >> 4; const int c_ = (f_ & 15) * 4; \
            CP16(smb + (uint32_t)(SK_OFF + (buf)*SK_BUF + r_*AST + c_) * 4, \
                 Kp + (size_t)((t0) + r_) * HDd + c_); \
            CP16(smb + (uint32_t)(SV_OFF + (buf)*SV_BUF + r_*VST + c_) * 4, \
                 Vp + (size_t)((t0) + r_) * HDd + c_); \
        } \
        CPCOMMIT(); \
    } while (0)

    KISSUE(0, 0);

    // stage Q (pre-scaled by 1/8; inputs already tf32-rounded)
#pragma unroll
    for (int i = 0; i < 16; i++) {
        const int f = tid + i * 128;            // 0..2047
        const int r = f >> 4, c = (f & 15) * 4;
        float4 qv = *(const float4*)(Qp + (size_t)r * HDd + c);
        qv.x *= 0.125f; qv.y *= 0.125f; qv.z *= 0.125f; qv.w *= 0.125f;
        *(float4*)(sm + r * AST + c) = qv;
    }

    float Of[2][8][4];
#pragma unroll
    for (int mt = 0; mt < 2; mt++)
#pragma unroll
        for (int nt = 0; nt < 8; nt++)
#pragma unroll
            for (int r = 0; r < 4; r++) Of[mt][nt][r] = 0.f;
    float m_[2][2] = {{-1e30f, -1e30f}, {-1e30f, -1e30f}};
    float l_[2][2] = {{0.f, 0.f}, {0.f, 0.f}};

    const int ntiles = qt * 4 + 4;
    const int my_last = qt * 4 + wq;       // this warp's diagonal tile

    for (int it = 0; it < ntiles; it++) {
        CPWAIT(0);
        __syncthreads();
        if (it + 1 < ntiles) KISSUE((it + 1) & 1, (it + 1) * 32);

        if (it <= my_last) {
            const uint32_t* K_ = (const uint32_t*)(sm + SK_OFF + (it & 1) * SK_BUF);
            const uint32_t* Q_ = (const uint32_t*)sm;
            float Sc[2][4][4];
#pragma unroll
            for (int mt = 0; mt < 2; mt++)
#pragma unroll
                for (int nt = 0; nt < 4; nt++)
#pragma unroll
                    for (int r = 0; r < 4; r++) Sc[mt][nt][r] = 0.f;

#pragma unroll
            for (int kt = 0; kt < 8; kt++) {
                uint32_t bk[4][2];
#pragma unroll
                for (int nt = 0; nt < 4; nt++) {
                    bk[nt][0] = K_[(nt * 8 + gr) * AST + kt * 8 + tg];
                    bk[nt][1] = K_[(nt * 8 + gr) * AST + kt * 8 + tg + 4];
                }
#pragma unroll
                for (int mt = 0; mt < 2; mt++) {
                    const int r = wq * 32 + mt * 16 + gr;
                    uint32_t aq[4];
                    aq[0] = Q_[r * AST + kt * 8 + tg];
                    aq[1] = Q_[(r + 8) * AST + kt * 8 + tg];
                    aq[2] = Q_[r * AST + kt * 8 + tg + 4];
                    aq[3] = Q_[(r + 8) * AST + kt * 8 + tg + 4];
#pragma unroll
                    for (int nt = 0; nt < 4; nt++)
                        mma_tf32(Sc[mt][nt], aq, bk[nt]);
                }
            }

            if (it == my_last) {           // diagonal tile: causal mask
                const int t0k = it * 32;
#pragma unroll
                for (int mt = 0; mt < 2; mt++) {
                    const int r0 = q0 + wq * 32 + mt * 16 + gr;
#pragma unroll
                    for (int nt = 0; nt < 4; nt++) {
                        const int key = t0k + nt * 8 + 2 * tg;
                        if (key > r0)        Sc[mt][nt][0] = -1e30f;
                        if (key + 1 > r0)    Sc[mt][nt][1] = -1e30f;
                        if (key > r0 + 8)    Sc[mt][nt][2] = -1e30f;
                        if (key + 1 > r0 + 8) Sc[mt][nt][3] = -1e30f;
                    }
                }
            }

            // online softmax: row max, rescale, exp, row sum
#pragma unroll
            for (int mt = 0; mt < 2; mt++)
#pragma unroll
                for (int h = 0; h < 2; h++) {
                    float tm = fmaxf(fmaxf(Sc[mt][0][2*h], Sc[mt][0][2*h+1]),
                                     fmaxf(Sc[mt][1][2*h], Sc[mt][1][2*h+1]));
                    tm = fmaxf(tm, fmaxf(fmaxf(Sc[mt][2][2*h], Sc[mt][2][2*h+1]),
                                         fmaxf(Sc[mt][3][2*h], Sc[mt][3][2*h+1])));
                    tm = fmaxf(tm, __shfl_xor_sync(0xffffffffu, tm, 1));
                    tm = fmaxf(tm, __shfl_xor_sync(0xffffffffu, tm, 2));
                    const float mnew = fmaxf(m_[mt][h], tm);
                    const float corr = __expf(m_[mt][h] - mnew);
                    m_[mt][h] = mnew;
                    l_[mt][h] *= corr;
#pragma unroll
                    for (int nt = 0; nt < 8; nt++) {
                        Of[mt][nt][2*h]     *= corr;
                        Of[mt][nt][2*h + 1] *= corr;
                    }
                }

            float rs[2][2] = {{0.f, 0.f}, {0.f, 0.f}};
#pragma unroll
            for (int mt = 0; mt < 2; mt++)
#pragma unroll
                for (int nt = 0; nt < 4; nt++) {
                    const float p0 = __expf(Sc[mt][nt][0] - m_[mt][0]);
                    const float p1 = __expf(Sc[mt][nt][1] - m_[mt][0]);
                    const float p2 = __expf(Sc[mt][nt][2] - m_[mt][1]);
                    const float p3 = __expf(Sc[mt][nt][3] - m_[mt][1]);
                    rs[mt][0] += p0 + p1;
                    rs[mt][1] += p2 + p3;
                    Sc[mt][nt][0] = to_tf32f(p0);
                    Sc[mt][nt][1] = to_tf32f(p1);
                    Sc[mt][nt][2] = to_tf32f(p2);
                    Sc[mt][nt][3] = to_tf32f(p3);
                }
#pragma unroll
            for (int mt = 0; mt < 2; mt++)
#pragma unroll
                for (int h = 0; h < 2; h++) {
                    float r = rs[mt][h];
                    r += __shfl_xor_sync(0xffffffffu, r, 1);
                    r += __shfl_xor_sync(0xffffffffu, r, 2);
                    l_[mt][h] += r;
                }

            // P @ V
            const uint32_t* V_ = (const uint32_t*)(sm + SV_OFF + (it & 1) * SV_BUF);
            const int qb = lane & 28;
#pragma unroll
            for (int kt = 0; kt < 4; kt++) {
                uint32_t ap[2][4];
#pragma unroll
                for (int mt = 0; mt < 2; mt++) {
                    const int s0 = qb + (tg >> 1);
                    const float x0 = __shfl_sync(0xffffffffu, Sc[mt][kt][0], s0);
                    const float x1 = __shfl_sync(0xffffffffu, Sc[mt][kt][1], s0);
                    const float x2 = __shfl_sync(0xffffffffu, Sc[mt][kt][2], s0);
                    const float x3 = __shfl_sync(0xffffffffu, Sc[mt][kt][3], s0);
                    const float y0 = __shfl_sync(0xffffffffu, Sc[mt][kt][0], s0 + 2);
                    const float y1 = __shfl_sync(0xffffffffu, Sc[mt][kt][1], s0 + 2);
                    const float y2 = __shfl_sync(0xffffffffu, Sc[mt][kt][2], s0 + 2);
                    const float y3 = __shfl_sync(0xffffffffu, Sc[mt][kt][3], s0 + 2);
                    ap[mt][0] = __float_as_uint((tg & 1) ? x1 : x0);  // (gr,   tg)
                    ap[mt][1] = __float_as_uint((tg & 1) ? x3 : x2);  // (gr+8, tg)
                    ap[mt][2] = __float_as_uint((tg & 1) ? y1 : y0);  // (gr,   tg+4)
                    ap[mt][3] = __float_as_uint((tg & 1) ? y3 : y2);  // (gr+8, tg+4)
                }
#pragma unroll
                for (int ntd = 0; ntd < 8; ntd++) {
                    uint32_t bv[2];
                    bv[0] = V_[(kt * 8 + tg) * VST + ntd * 8 + gr];
                    bv[1] = V_[(kt * 8 + tg + 4) * VST + ntd * 8 + gr];
                    mma_tf32(Of[0][ntd], ap[0], bv);
                    mma_tf32(Of[1][ntd], ap[1], bv);
                }
            }
        }
    }
#undef KISSUE

    // epilogue -> concat layout (tf32-rounded for the out gemm)
    float inv[2][2];
#pragma unroll
    for (int mt = 0; mt < 2; mt++) {
        inv[mt][0] = 1.f / l_[mt][0];
        inv[mt][1] = 1.f / l_[mt][1];
    }
    const int b_ = bh >> 4, h_ = bh & 15;
#pragma unroll
    for (int mt = 0; mt < 2; mt++) {
        const int r0 = q0 + wq * 32 + mt * 16 + gr;
        float* o0 = g_scratch + OFF_CAT + ((size_t)(b_ * Ss + r0)) * Dd + h_ * 64;
        float* o1 = g_scratch + OFF_CAT + ((size_t)(b_ * Ss + r0 + 8)) * Dd + h_ * 64;
#pragma unroll
        for (int ntd = 0; ntd < 8; ntd++) {
            const int col = ntd * 8 + 2 * tg;
            float2 v0, v1;
            v0.x = to_tf32f(Of[mt][ntd][0] * inv[mt][0]);
            v0.y = to_tf32f(Of[mt][ntd][1] * inv[mt][0]);
            v1.x = to_tf32f(Of[mt][ntd][2] * inv[mt][1]);
            v1.y = to_tf32f(Of[mt][ntd][3] * inv[mt][1]);
            *(float2*)(o0 + col) = v0;
            *(float2*)(o1 + col) = v1;
        }
    }
}

// ---------------------------------------------------------------------------
extern "C" void kernel_launch(void* const* d_in, const int* in_sizes, int n_in,
                              void* d_out, int out_size)
{
    const float* q_in = (const float*)d_in[0];
    const float* k_in = (const float*)d_in[1];
    const float* v_in = (const float*)d_in[2];
    const float* Wq   = (const float*)d_in[3];
    const float* bq   = (const float*)d_in[4];
    const float* Wk   = (const float*)d_in[5];
    const float* bk   = (const float*)d_in[6];
    const float* Wv   = (const float*)d_in[7];
    const float* bv   = (const float*)d_in[8];
    const float* Wo   = (const float*)d_in[9];
    const float* bo   = (const float*)d_in[10];
    float* out = (float*)d_out;

    cudaFuncSetAttribute(gemm_qkv_mma_kernel,
                         cudaFuncAttributeMaxDynamicSharedMemorySize, GEMM_SMEM_BYTES);
    cudaFuncSetAttribute(gemm_out_mma_kernel,
                         cudaFuncAttributeMaxDynamicSharedMemorySize, GEMM_SMEM_BYTES);
    cudaFuncSetAttribute(attn_mma_kernel,
                         cudaFuncAttributeMaxDynamicSharedMemorySize, ATTN_SMEM_BYTES);

    round_inputs_kernel<<<dim3(QKV_ELEMS / 1024, 3), 256>>>(q_in, k_in, v_in);
    transpose_w_kernel<<<dim3(32, 32, 4), dim3(32, 8)>>>(Wq, Wk, Wv, Wo);

    gemm_qkv_mma_kernel<<<dim3(8, 32, 3), 256, GEMM_SMEM_BYTES>>>(bq, bk, bv);

    attn_mma_kernel<<<dim3(16, Bb * Hh), 128, ATTN_SMEM_BYTES>>>();

    gemm_out_mma_kernel<<<dim3(8, 32), 256, GEMM_SMEM_BYTES>>>(bo, out);
}

// round 6
// speedup vs baseline: 3.6460x; 1.0460x over previous
#include <cuda_runtime.h>
#include <cstdint>

#define Bb 2
#define Ss 2048
#define Dd 1024
#define Hh 16
#define HDd 64
#define QKV_ELEMS (Bb*Hh*Ss*HDd)   // 4194304
#define WT_ELEMS (Dd*Dd)           // 1048576

#define OFF_CAT (3ull*QKV_ELEMS)
#define OFF_WT  (4ull*QKV_ELEMS)
#define OFF_AR  (4ull*QKV_ELEMS + 4ull*WT_ELEMS)

// q,k,v,concat, WT x4, rounded inputs x3
static __device__ float g_scratch[7ull*QKV_ELEMS + 4ull*WT_ELEMS];

// ---------------------------------------------------------------------------
__device__ __forceinline__ uint32_t smem_u32(const void* p) {
    uint32_t a;
    asm("{ .reg .u64 t; cvta.to.shared.u64 t, %1; cvt.u32.u64 %0, t; }"
        : "=r"(a) : "l"(p));
    return a;
}
__device__ __forceinline__ float to_tf32f(float x) {
    uint32_t y; asm("cvt.rna.tf32.f32 %0, %1;" : "=r"(y) : "f"(x));
    return __uint_as_float(y);
}
__device__ __forceinline__ void mma_tf32(float* c, const uint32_t* a, const uint32_t* b) {
    asm volatile(
        "mma.sync.aligned.m16n8k8.row.col.f32.tf32.tf32.f32 "
        "{%0,%1,%2,%3}, {%4,%5,%6,%7}, {%8,%9}, {%0,%1,%2,%3};"
        : "+f"(c[0]), "+f"(c[1]), "+f"(c[2]), "+f"(c[3])
        : "r"(a[0]), "r"(a[1]), "r"(a[2]), "r"(a[3]), "r"(b[0]), "r"(b[1]));
}
#define CP16(smem_addr, gptr) \
    asm volatile("cp.async.ca.shared.global [%0], [%1], 16;" \
                 :: "r"(smem_addr), "l"(gptr) : "memory")
#define CPCOMMIT() asm volatile("cp.async.commit_group;" ::: "memory")
#define CPWAIT(N)  asm volatile("cp.async.wait_group %0;" :: "n"(N) : "memory")

// ---------------------------------------------------------------------------
// Prep: round activations to tf32 (stored as fp32 bit patterns)
// ---------------------------------------------------------------------------
__global__ __launch_bounds__(256) void round_inputs_kernel(
    const float* __restrict__ q, const float* __restrict__ k,
    const float* __restrict__ v)
{
    const int z = blockIdx.y;
    const float* in = (z == 0) ? q : ((z == 1) ? k : v);
    float* out = g_scratch + OFF_AR + (size_t)z * QKV_ELEMS;
    const size_t i = ((size_t)blockIdx.x * 256 + threadIdx.x) * 4;
    float4 t = *(const float4*)(in + i);
    t.x = to_tf32f(t.x); t.y = to_tf32f(t.y);
    t.z = to_tf32f(t.z); t.w = to_tf32f(t.w);
    *(float4*)(out + i) = t;
}

// Weight transpose + round: WT[n][k] = tf32(W[k][n])
__global__ __launch_bounds__(256) void transpose_w_kernel(
    const float* __restrict__ Wq, const float* __restrict__ Wk,
    const float* __restrict__ Wv, const float* __restrict__ Wo)
{
    __shared__ float t[32][33];
    const int z = blockIdx.z;
    const float* W = (z == 0) ? Wq : ((z == 1) ? Wk : ((z == 2) ? Wv : Wo));
    float* WT = g_scratch + OFF_WT + (size_t)z * WT_ELEMS;
    const int x0 = blockIdx.x * 32, y0 = blockIdx.y * 32;
    const int tx = threadIdx.x, ty = threadIdx.y;
#pragma unroll
    for (int j = 0; j < 32; j += 8)
        t[ty + j][tx] = W[(size_t)(y0 + ty + j) * Dd + x0 + tx];
    __syncthreads();
#pragma unroll
    for (int j = 0; j < 32; j += 8)
        WT[(size_t)(x0 + ty + j) * Dd + y0 + tx] = to_tf32f(t[tx][ty + j]);
}

// ---------------------------------------------------------------------------
// tf32 mma.sync GEMM with 4-stage cp.async pipeline.
// A, BT already tf32-rounded. 128x128 CTA tile, BK=16, 8 warps (2x4).
// SPLIT=1 also tf32-rounds the stored outputs (consumed by mma attention).
// ---------------------------------------------------------------------------
#define KST 20
#define TILE_F (128 * KST)        // 2560 floats
#define STAGE_F (2 * TILE_F)      // 5120 floats
#define NSTAGE 4
#define GEMM_SMEM_BYTES (NSTAGE * STAGE_F * 4)   // 81920

template<int SPLIT>
__device__ __forceinline__ void gemm_mma(const float* __restrict__ A,
                                         const float* __restrict__ BT,
                                         const float* __restrict__ bias,
                                         float* __restrict__ C)
{
    extern __shared__ float smf[];

    const int tid = threadIdx.x;
    const int wid = tid >> 5, lane = tid & 31;
    const int m0 = blockIdx.y * 128, n0 = blockIdx.x * 128;

    const int row0 = tid >> 2, c4 = tid & 3;
    const uint32_t so0 = row0 * 80 + c4 * 16;          // bytes
    const uint32_t so1 = (row0 + 64) * 80 + c4 * 16;
    const float* gA0 = A  + (size_t)(m0 + row0) * Dd + c4 * 4;
    const float* gA1 = A  + (size_t)(m0 + row0 + 64) * Dd + c4 * 4;
    const float* gB0 = BT + (size_t)(n0 + row0) * Dd + c4 * 4;
    const float* gB1 = BT + (size_t)(n0 + row0 + 64) * Dd + c4 * 4;
    const uint32_t sbase = smem_u32(smf);

    const int wm = wid >> 2, wn = wid & 3;
    const int mbw = wm * 64, nbw = wn * 32;
    const int gr = lane >> 2, ck = lane & 3;

    float acc[4][4][4];
#pragma unroll
    for (int i = 0; i < 4; i++)
#pragma unroll
        for (int j = 0; j < 4; j++)
#pragma unroll
            for (int r = 0; r < 4; r++) acc[i][j][r] = 0.f;

#define GISSUE(buf, k0) do { \
        uint32_t a_ = sbase + (uint32_t)(buf) * (STAGE_F * 4); \
        uint32_t b_ = a_ + TILE_F * 4; \
        CP16(a_ + so0, gA0 + (k0)); CP16(a_ + so1, gA1 + (k0)); \
        CP16(b_ + so0, gB0 + (k0)); CP16(b_ + so1, gB1 + (k0)); \
        CPCOMMIT(); \
    } while (0)

    GISSUE(0, 0); GISSUE(1, 16); GISSUE(2, 32);

    const int NIT = Dd / 16;   // 64
    for (int it = 0; it < NIT; ++it) {
        CPWAIT(2);
        __syncthreads();
        if (it + 3 < NIT) GISSUE((it + 3) & 3, (it + 3) * 16);

        const uint32_t* SA = (const uint32_t*)(smf + (size_t)(it & 3) * STAGE_F);
        const uint32_t* SB = SA + TILE_F;
#pragma unroll
        for (int ks = 0; ks < 2; ks++) {
            const int kof = ks * 8;
            uint32_t bf[4][2];
#pragma unroll
            for (int nt = 0; nt < 4; nt++) {
                const int nb = (nbw + nt * 8 + gr) * KST + kof + ck;
                bf[nt][0] = SB[nb];
                bf[nt][1] = SB[nb + 4];
            }
#pragma unroll
            for (int mt = 0; mt < 4; mt++) {
                const int ab = (mbw + mt * 16 + gr) * KST + kof + ck;
                uint32_t af[4];
                af[0] = SA[ab];
                af[1] = SA[ab + 8 * KST];
                af[2] = SA[ab + 4];
                af[3] = SA[ab + 8 * KST + 4];
#pragma unroll
                for (int nt = 0; nt < 4; nt++)
                    mma_tf32(acc[mt][nt], af, bf[nt]);
            }
        }
    }
#undef GISSUE

#pragma unroll
    for (int mt = 0; mt < 4; mt++) {
        const int row = m0 + mbw + mt * 16 + gr;
#pragma unroll
        for (int nt = 0; nt < 4; nt++) {
            const int col = n0 + nbw + nt * 8 + 2 * ck;
            const float2 bi = *(const float2*)(bias + col);
            float2 v0, v1;
            v0.x = acc[mt][nt][0] + bi.x; v0.y = acc[mt][nt][1] + bi.y;
            v1.x = acc[mt][nt][2] + bi.x; v1.y = acc[mt][nt][3] + bi.y;
            if (SPLIT) {
                // round for the tf32 mma attention consumer
                v0.x = to_tf32f(v0.x); v0.y = to_tf32f(v0.y);
                v1.x = to_tf32f(v1.x); v1.y = to_tf32f(v1.y);
                const int h = col >> 6, d = col & 63;
                const int b0_ = row >> 11, s0 = row & 2047;
                *(float2*)&C[(((size_t)(b0_ * Hh + h)) * Ss + s0) * HDd + d] = v0;
                const int row1 = row + 8;
                const int b1_ = row1 >> 11, s1 = row1 & 2047;
                *(float2*)&C[(((size_t)(b1_ * Hh + h)) * Ss + s1) * HDd + d] = v1;
            } else {
                *(float2*)&C[(size_t)row * Dd + col] = v0;
                *(float2*)&C[(size_t)(row + 8) * Dd + col] = v1;
            }
        }
    }
}

__global__ __launch_bounds__(256, 2) void gemm_qkv_mma_kernel(
    const float* __restrict__ bq, const float* __restrict__ bk,
    const float* __restrict__ bv)
{
    const int z = blockIdx.z;
    const float* A    = g_scratch + OFF_AR + (size_t)z * QKV_ELEMS;
    const float* bias = (z == 0) ? bq : ((z == 1) ? bk : bv);
    const float* BT   = g_scratch + OFF_WT + (size_t)z * WT_ELEMS;
    float* C = g_scratch + (size_t)z * QKV_ELEMS;
    gemm_mma<1>(A, BT, bias, C);
}

__global__ __launch_bounds__(256, 2) void gemm_out_mma_kernel(
    const float* __restrict__ bo, float* __restrict__ out)
{
    const float* A  = g_scratch + OFF_CAT;                 // concat (pre-rounded)
    const float* BT = g_scratch + OFF_WT + 3ull * WT_ELEMS;
    gemm_mma<0>(A, BT, bo, out);
}

// ---------------------------------------------------------------------------
// MMA flash attention (tf32), causal. CTA: 128 queries, 4 warps x 32 rows.
// K/V tiles of 32 keys, cp.async double-buffered. Online softmax in fragments,
// log2-domain (Q pre-scaled by log2(e)/8, re-rounded rna to tf32).
// 3 CTAs/SM, 1D heavy-first grid.
// ---------------------------------------------------------------------------
#define AST 68                        // sQ/sK row stride (floats)
#define VST 72                        // sV row stride
#define SK_OFF (128*AST)              // 8704
#define SK_BUF (32*AST)               // 2176
#define SV_OFF (SK_OFF + 2*SK_BUF)    // 13056
#define SV_BUF (32*VST)               // 2304
#define ATTN_SMEM_BYTES ((SV_OFF + 2*SV_BUF) * 4)   // 70656

__global__ __launch_bounds__(128, 3) void attn_mma_kernel()
{
    extern __shared__ float sm[];
    const int bx = blockIdx.x;
    const int qt = 15 - (bx >> 5);         // heavy CTAs launch first
    const int bh = bx & 31;
    const int q0 = qt * 128;
    const int tid = threadIdx.x;
    const int wq = tid >> 5, lane = tid & 31;
    const int gr = lane >> 2, tg = lane & 3;

    const float* Qp = g_scratch + (size_t)bh * (Ss * HDd) + (size_t)q0 * HDd;
    const float* Kp = g_scratch + (size_t)QKV_ELEMS     + (size_t)bh * (Ss * HDd);
    const float* Vp = g_scratch + 2ull * QKV_ELEMS      + (size_t)bh * (Ss * HDd);

    const uint32_t smb = smem_u32(sm);

#define KISSUE(buf, t0) do { \
        _Pragma("unroll") \
        for (int j_ = 0; j_ < 4; j_++) { \
            const int f_ = tid + j_ * 128; \
            const int r_ = f_ >> 4; const int c_ = (f_ & 15) * 4; \
            CP16(smb + (uint32_t)(SK_OFF + (buf)*SK_BUF + r_*AST + c_) * 4, \
                 Kp + (size_t)((t0) + r_) * HDd + c_); \
            CP16(smb + (uint32_t)(SV_OFF + (buf)*SV_BUF + r_*VST + c_) * 4, \
                 Vp + (size_t)((t0) + r_) * HDd + c_); \
        } \
        CPCOMMIT(); \
    } while (0)

    KISSUE(0, 0);

    // stage Q, pre-scaled by log2(e)/8 and re-rounded to tf32 (rna)
    const float qsc = 0.18033688011112042f;   // 1.4426950408889634 / 8
#pragma unroll
    for (int i = 0; i < 16; i++) {
        const int f = tid + i * 128;            // 0..2047
        const int r = f >> 4, c = (f & 15) * 4;
        float4 qv = *(const float4*)(Qp + (size_t)r * HDd + c);
        qv.x = to_tf32f(qv.x * qsc); qv.y = to_tf32f(qv.y * qsc);
        qv.z = to_tf32f(qv.z * qsc); qv.w = to_tf32f(qv.w * qsc);
        *(float4*)(sm + r * AST + c) = qv;
    }

    float Of[2][8][4];
#pragma unroll
    for (int mt = 0; mt < 2; mt++)
#pragma unroll
        for (int nt = 0; nt < 8; nt++)
#pragma unroll
            for (int r = 0; r < 4; r++) Of[mt][nt][r] = 0.f;
    float m_[2][2] = {{-1e30f, -1e30f}, {-1e30f, -1e30f}};
    float l_[2][2] = {{0.f, 0.f}, {0.f, 0.f}};

    const int ntiles = qt * 4 + 4;
    const int my_last = qt * 4 + wq;       // this warp's diagonal tile

    for (int it = 0; it < ntiles; it++) {
        CPWAIT(0);
        __syncthreads();
        if (it + 1 < ntiles) KISSUE((it + 1) & 1, (it + 1) * 32);

        if (it <= my_last) {
            const uint32_t* K_ = (const uint32_t*)(sm + SK_OFF + (it & 1) * SK_BUF);
            const uint32_t* Q_ = (const uint32_t*)sm;
            float Sc[2][4][4];
#pragma unroll
            for (int mt = 0; mt < 2; mt++)
#pragma unroll
                for (int nt = 0; nt < 4; nt++)
#pragma unroll
                    for (int r = 0; r < 4; r++) Sc[mt][nt][r] = 0.f;

#pragma unroll
            for (int kt = 0; kt < 8; kt++) {
                uint32_t bk[4][2];
#pragma unroll
                for (int nt = 0; nt < 4; nt++) {
                    bk[nt][0] = K_[(nt * 8 + gr) * AST + kt * 8 + tg];
                    bk[nt][1] = K_[(nt * 8 + gr) * AST + kt * 8 + tg + 4];
                }
#pragma unroll
                for (int mt = 0; mt < 2; mt++) {
                    const int r = wq * 32 + mt * 16 + gr;
                    uint32_t aq[4];
                    aq[0] = Q_[r * AST + kt * 8 + tg];
                    aq[1] = Q_[(r + 8) * AST + kt * 8 + tg];
                    aq[2] = Q_[r * AST + kt * 8 + tg + 4];
                    aq[3] = Q_[(r + 8) * AST + kt * 8 + tg + 4];
#pragma unroll
                    for (int nt = 0; nt < 4; nt++)
                        mma_tf32(Sc[mt][nt], aq, bk[nt]);
                }
            }

            if (it == my_last) {           // diagonal tile: causal mask
                const int t0k = it * 32;
#pragma unroll
                for (int mt = 0; mt < 2; mt++) {
                    const int r0 = q0 + wq * 32 + mt * 16 + gr;
#pragma unroll
                    for (int nt = 0; nt < 4; nt++) {
                        const int key = t0k + nt * 8 + 2 * tg;
                        if (key > r0)        Sc[mt][nt][0] = -1e30f;
                        if (key + 1 > r0)    Sc[mt][nt][1] = -1e30f;
                        if (key > r0 + 8)    Sc[mt][nt][2] = -1e30f;
                        if (key + 1 > r0 + 8) Sc[mt][nt][3] = -1e30f;
                    }
                }
            }

            // online softmax (log2 domain): row max, rescale, exp2, row sum
#pragma unroll
            for (int mt = 0; mt < 2; mt++)
#pragma unroll
                for (int h = 0; h < 2; h++) {
                    float tm = fmaxf(fmaxf(Sc[mt][0][2*h], Sc[mt][0][2*h+1]),
                                     fmaxf(Sc[mt][1][2*h], Sc[mt][1][2*h+1]));
                    tm = fmaxf(tm, fmaxf(fmaxf(Sc[mt][2][2*h], Sc[mt][2][2*h+1]),
                                         fmaxf(Sc[mt][3][2*h], Sc[mt][3][2*h+1])));
                    tm = fmaxf(tm, __shfl_xor_sync(0xffffffffu, tm, 1));
                    tm = fmaxf(tm, __shfl_xor_sync(0xffffffffu, tm, 2));
                    const float mnew = fmaxf(m_[mt][h], tm);
                    const float corr = exp2f(m_[mt][h] - mnew);
                    m_[mt][h] = mnew;
                    l_[mt][h] *= corr;
#pragma unroll
                    for (int nt = 0; nt < 8; nt++) {
                        Of[mt][nt][2*h]     *= corr;
                        Of[mt][nt][2*h + 1] *= corr;
                    }
                }

            float rs[2][2] = {{0.f, 0.f}, {0.f, 0.f}};
#pragma unroll
            for (int mt = 0; mt < 2; mt++)
#pragma unroll
                for (int nt = 0; nt < 4; nt++) {
                    const float p0 = exp2f(Sc[mt][nt][0] - m_[mt][0]);
                    const float p1 = exp2f(Sc[mt][nt][1] - m_[mt][0]);
                    const float p2 = exp2f(Sc[mt][nt][2] - m_[mt][1]);
                    const float p3 = exp2f(Sc[mt][nt][3] - m_[mt][1]);
                    rs[mt][0] += p0 + p1;
                    rs[mt][1] += p2 + p3;
                    Sc[mt][nt][0] = to_tf32f(p0);
                    Sc[mt][nt][1] = to_tf32f(p1);
                    Sc[mt][nt][2] = to_tf32f(p2);
                    Sc[mt][nt][3] = to_tf32f(p3);
                }
#pragma unroll
            for (int mt = 0; mt < 2; mt++)
#pragma unroll
                for (int h = 0; h < 2; h++) {
                    float r = rs[mt][h];
                    r += __shfl_xor_sync(0xffffffffu, r, 1);
                    r += __shfl_xor_sync(0xffffffffu, r, 2);
                    l_[mt][h] += r;
                }

            // P @ V
            const uint32_t* V_ = (const uint32_t*)(sm + SV_OFF + (it & 1) * SV_BUF);
            const int qb = lane & 28;
#pragma unroll
            for (int kt = 0; kt < 4; kt++) {
                uint32_t ap[2][4];
#pragma unroll
                for (int mt = 0; mt < 2; mt++) {
                    const int s0 = qb + (tg >> 1);
                    const float x0 = __shfl_sync(0xffffffffu, Sc[mt][kt][0], s0);
                    const float x1 = __shfl_sync(0xffffffffu, Sc[mt][kt][1], s0);
                    const float x2 = __shfl_sync(0xffffffffu, Sc[mt][kt][2], s0);
                    const float x3 = __shfl_sync(0xffffffffu, Sc[mt][kt][3], s0);
                    const float y0 = __shfl_sync(0xffffffffu, Sc[mt][kt][0], s0 + 2);
                    const float y1 = __shfl_sync(0xffffffffu, Sc[mt][kt][1], s0 + 2);
                    const float y2 = __shfl_sync(0xffffffffu, Sc[mt][kt][2], s0 + 2);
                    const float y3 = __shfl_sync(0xffffffffu, Sc[mt][kt][3], s0 + 2);
                    ap[mt][0] = __float_as_uint((tg & 1) ? x1 : x0);  // (gr,   tg)
                    ap[mt][1] = __float_as_uint((tg & 1) ? x3 : x2);  // (gr+8, tg)
                    ap[mt][2] = __float_as_uint((tg & 1) ? y1 : y0);  // (gr,   tg+4)
                    ap[mt][3] = __float_as_uint((tg & 1) ? y3 : y2);  // (gr+8, tg+4)
                }
#pragma unroll
                for (int ntd = 0; ntd < 8; ntd++) {
                    uint32_t bv[2];
                    bv[0] = V_[(kt * 8 + tg) * VST + ntd * 8 + gr];
                    bv[1] = V_[(kt * 8 + tg + 4) * VST + ntd * 8 + gr];
                    mma_tf32(Of[0][ntd], ap[0], bv);
                    mma_tf32(Of[1][ntd], ap[1], bv);
                }
            }
        }
    }
#undef KISSUE

    // epilogue -> concat layout (tf32-rounded for the out gemm)
    float inv[2][2];
#pragma unroll
    for (int mt = 0; mt < 2; mt++) {
        inv[mt][0] = 1.f / l_[mt][0];
        inv[mt][1] = 1.f / l_[mt][1];
    }
    const int b_ = bh >> 4, h_ = bh & 15;
#pragma unroll
    for (int mt = 0; mt < 2; mt++) {
        const int r0 = q0 + wq * 32 + mt * 16 + gr;
        float* o0 = g_scratch + OFF_CAT + ((size_t)(b_ * Ss + r0)) * Dd + h_ * 64;
        float* o1 = g_scratch + OFF_CAT + ((size_t)(b_ * Ss + r0 + 8)) * Dd + h_ * 64;
#pragma unroll
        for (int ntd = 0; ntd < 8; ntd++) {
            const int col = ntd * 8 + 2 * tg;
            float2 v0, v1;
            v0.x = to_tf32f(Of[mt][ntd][0] * inv[mt][0]);
            v0.y = to_tf32f(Of[mt][ntd][1] * inv[mt][0]);
            v1.x = to_tf32f(Of[mt][ntd][2] * inv[mt][1]);
            v1.y = to_tf32f(Of[mt][ntd][3] * inv[mt][1]);
            *(float2*)(o0 + col) = v0;
            *(float2*)(o1 + col) = v1;
        }
    }
}

// ---------------------------------------------------------------------------
extern "C" void kernel_launch(void* const* d_in, const int* in_sizes, int n_in,
                              void* d_out, int out_size)
{
    const float* q_in = (const float*)d_in[0];
    const float* k_in = (const float*)d_in[1];
    const float* v_in = (const float*)d_in[2];
    const float* Wq   = (const float*)d_in[3];
    const float* bq   = (const float*)d_in[4];
    const float* Wk   = (const float*)d_in[5];
    const float* bk   = (const float*)d_in[6];
    const float* Wv   = (const float*)d_in[7];
    const float* bv   = (const float*)d_in[8];
    const float* Wo   = (const float*)d_in[9];
    const float* bo   = (const float*)d_in[10];
    float* out = (float*)d_out;

    cudaFuncSetAttribute(gemm_qkv_mma_kernel,
                         cudaFuncAttributeMaxDynamicSharedMemorySize, GEMM_SMEM_BYTES);
    cudaFuncSetAttribute(gemm_out_mma_kernel,
                         cudaFuncAttributeMaxDynamicSharedMemorySize, GEMM_SMEM_BYTES);
    cudaFuncSetAttribute(attn_mma_kernel,
                         cudaFuncAttributeMaxDynamicSharedMemorySize, ATTN_SMEM_BYTES);

    round_inputs_kernel<<<dim3(QKV_ELEMS / 1024, 3), 256>>>(q_in, k_in, v_in);
    transpose_w_kernel<<<dim3(32, 32, 4), dim3(32, 8)>>>(Wq, Wk, Wv, Wo);

    gemm_qkv_mma_kernel<<<dim3(8, 32, 3), 256, GEMM_SMEM_BYTES>>>(bq, bk, bv);

    attn_mma_kernel<<<512, 128, ATTN_SMEM_BYTES>>>();

    gemm_out_mma_kernel<<<dim3(8, 32), 256, GEMM_SMEM_BYTES>>>(bo, out);
}

// round 7
// speedup vs baseline: 3.7712x; 1.0343x over previous
#include <cuda_runtime.h>
#include <cstdint>

#define Bb 2
#define Ss 2048
#define Dd 1024
#define Hh 16
#define HDd 64
#define QKV_ELEMS (Bb*Hh*Ss*HDd)   // 4194304
#define WT_ELEMS (Dd*Dd)           // 1048576

#define OFF_CAT (3ull*QKV_ELEMS)
#define OFF_WT  (4ull*QKV_ELEMS)
#define OFF_AR  (4ull*QKV_ELEMS + 4ull*WT_ELEMS)

// q,k,v,concat, WT x4, rounded inputs x3   (k-dims stored 8-group interleaved)
static __device__ float g_scratch[7ull*QKV_ELEMS + 4ull*WT_ELEMS];

// ---------------------------------------------------------------------------
__device__ __forceinline__ uint32_t smem_u32(const void* p) {
    uint32_t a;
    asm("{ .reg .u64 t; cvta.to.shared.u64 t, %1; cvt.u32.u64 %0, t; }"
        : "=r"(a) : "l"(p));
    return a;
}
__device__ __forceinline__ float to_tf32f(float x) {
    uint32_t y; asm("cvt.rna.tf32.f32 %0, %1;" : "=r"(y) : "f"(x));
    return __uint_as_float(y);
}
__device__ __forceinline__ void mma_tf32(float* c, const uint32_t* a, const uint32_t* b) {
    asm volatile(
        "mma.sync.aligned.m16n8k8.row.col.f32.tf32.tf32.f32 "
        "{%0,%1,%2,%3}, {%4,%5,%6,%7}, {%8,%9}, {%0,%1,%2,%3};"
        : "+f"(c[0]), "+f"(c[1]), "+f"(c[2]), "+f"(c[3])
        : "r"(a[0]), "r"(a[1]), "r"(a[2]), "r"(a[3]), "r"(b[0]), "r"(b[1]));
}
#define CP16(smem_addr, gptr) \
    asm volatile("cp.async.ca.shared.global [%0], [%1], 16;" \
                 :: "r"(smem_addr), "l"(gptr) : "memory")
#define CPCOMMIT() asm volatile("cp.async.commit_group;" ::: "memory")
#define CPWAIT(N)  asm volatile("cp.async.wait_group %0;" :: "n"(N) : "memory")

// ---------------------------------------------------------------------------
// Prep: round to tf32 + interleave k within 8-groups: pos p holds col (p>>1)+(p&1)*4
// ---------------------------------------------------------------------------
__global__ __launch_bounds__(256) void round_inputs_kernel(
    const float* __restrict__ q, const float* __restrict__ k,
    const float* __restrict__ v)
{
    const int z = blockIdx.y;
    const float* in = (z == 0) ? q : ((z == 1) ? k : v);
    float* out = g_scratch + OFF_AR + (size_t)z * QKV_ELEMS;
    const size_t i = ((size_t)blockIdx.x * 256 + threadIdx.x) * 8;
    float4 lo = *(const float4*)(in + i);
    float4 hi = *(const float4*)(in + i + 4);
    float4 o0, o1;
    o0.x = to_tf32f(lo.x); o0.y = to_tf32f(hi.x);
    o0.z = to_tf32f(lo.y); o0.w = to_tf32f(hi.y);
    o1.x = to_tf32f(lo.z); o1.y = to_tf32f(hi.z);
    o1.z = to_tf32f(lo.w); o1.w = to_tf32f(hi.w);
    *(float4*)(out + i)     = o0;
    *(float4*)(out + i + 4) = o1;
}

// Weight transpose + round + k-interleave: WT[n][pos(k)] = tf32(W[k][n])
__global__ __launch_bounds__(256) void transpose_w_kernel(
    const float* __restrict__ Wq, const float* __restrict__ Wk,
    const float* __restrict__ Wv, const float* __restrict__ Wo)
{
    __shared__ float t[32][33];
    const int z = blockIdx.z;
    const float* W = (z == 0) ? Wq : ((z == 1) ? Wk : ((z == 2) ? Wv : Wo));
    float* WT = g_scratch + OFF_WT + (size_t)z * WT_ELEMS;
    const int x0 = blockIdx.x * 32, y0 = blockIdx.y * 32;
    const int tx = threadIdx.x, ty = threadIdx.y;
#pragma unroll
    for (int j = 0; j < 32; j += 8)
        t[ty + j][tx] = W[(size_t)(y0 + ty + j) * Dd + x0 + tx];
    __syncthreads();
    // k-col y0+tx -> position within 8-group: pos(c)=2*(c&3)+(c>>2)
    const int kp = y0 + (tx & 24) + 2 * (tx & 3) + ((tx >> 2) & 1);
#pragma unroll
    for (int j = 0; j < 32; j += 8)
        WT[(size_t)(x0 + ty + j) * Dd + kp] = to_tf32f(t[tx][ty + j]);
}

// ---------------------------------------------------------------------------
// tf32 mma.sync GEMM, 5-stage cp.async pipeline, packed stride-16 tiles with
// per-row ks-group swap -> conflict-free LDS.64 fragment loads.
// A,BT pre-rounded + k-interleaved in gmem.
// ---------------------------------------------------------------------------
#define TILE_F (128 * 16)         // 2048 floats per matrix tile
#define STAGE_F (2 * TILE_F)      // 4096
#define NSTAGE 5
#define GEMM_SMEM_BYTES (NSTAGE * STAGE_F * 4)   // 81920

template<int SPLIT>
__device__ __forceinline__ void gemm_mma(const float* __restrict__ A,
                                         const float* __restrict__ BT,
                                         const float* __restrict__ bias,
                                         float* __restrict__ C)
{
    extern __shared__ float smf[];

    const int tid = threadIdx.x;
    const int wid = tid >> 5, lane = tid & 31;
    const int m0 = blockIdx.y * 128, n0 = blockIdx.x * 128;

    // loader: thread -> rows (row0, row0+64), 16B chunk c4 (of 4 per row)
    const int row0 = tid >> 2, c4 = tid & 3;
    const int swp = ((c4 >> 1) ^ ((row0 >> 1) & 1)) << 3;
    const uint32_t so0 = (uint32_t)(row0 * 16 + swp + (c4 & 1) * 4) * 4;
    const uint32_t so1 = so0 + 64 * 16 * 4;   // (row0+64): same swap bit
    const float* gA0 = A  + (size_t)(m0 + row0) * Dd + c4 * 4;
    const float* gA1 = A  + (size_t)(m0 + row0 + 64) * Dd + c4 * 4;
    const float* gB0 = BT + (size_t)(n0 + row0) * Dd + c4 * 4;
    const float* gB1 = BT + (size_t)(n0 + row0 + 64) * Dd + c4 * 4;
    const uint32_t sbase = smem_u32(smf);

    const int wm = wid >> 2, wn = wid & 3;
    const int mbw = wm * 64, nbw = wn * 32;
    const int gr = lane >> 2, ck = lane & 3;

    float acc[4][4][4];
#pragma unroll
    for (int i = 0; i < 4; i++)
#pragma unroll
        for (int j = 0; j < 4; j++)
#pragma unroll
            for (int r = 0; r < 4; r++) acc[i][j][r] = 0.f;

#define GISSUE(buf, k0) do { \
        uint32_t a_ = sbase + (uint32_t)(buf) * (STAGE_F * 4); \
        uint32_t b_ = a_ + TILE_F * 4; \
        CP16(a_ + so0, gA0 + (k0)); CP16(a_ + so1, gA1 + (k0)); \
        CP16(b_ + so0, gB0 + (k0)); CP16(b_ + so1, gB1 + (k0)); \
        CPCOMMIT(); \
    } while (0)

    GISSUE(0, 0); GISSUE(1, 16); GISSUE(2, 32); GISSUE(3, 48);

    const int NIT = Dd / 16;   // 64
    const int swk = (gr >> 1) & 1;
    for (int it = 0; it < NIT; ++it) {
        CPWAIT(3);
        __syncthreads();
        if (it + 4 < NIT) GISSUE((it + 4) % NSTAGE, (it + 4) * 16);
        else CPCOMMIT();   // keep group count invariant (tail correctness)

        const uint32_t* SA = (const uint32_t*)(smf + (size_t)(it % NSTAGE) * STAGE_F);
        const uint32_t* SB = SA + TILE_F;
#pragma unroll
        for (int ks = 0; ks < 2; ks++) {
            const int ko = ((ks ^ swk) << 3) + 2 * ck;
            uint2 bfr[4];
#pragma unroll
            for (int nt = 0; nt < 4; nt++)
                bfr[nt] = *(const uint2*)&SB[(nbw + nt * 8 + gr) * 16 + ko];
#pragma unroll
            for (int mt = 0; mt < 4; mt++) {
                const int rb = (mbw + mt * 16 + gr) * 16 + ko;
                const uint2 a01 = *(const uint2*)&SA[rb];
                const uint2 a23 = *(const uint2*)&SA[rb + 8 * 16];
                uint32_t af[4] = {a01.x, a23.x, a01.y, a23.y};
#pragma unroll
                for (int nt = 0; nt < 4; nt++)
                    mma_tf32(acc[mt][nt], af, (const uint32_t*)&bfr[nt]);
            }
        }
    }
#undef GISSUE

    // epilogue with bias
    const int p0 = ((ck & 1) << 2) + (ck >> 1);   // pos(2ck); pos(2ck+1)=p0+2
#pragma unroll
    for (int mt = 0; mt < 4; mt++) {
        const int row = m0 + mbw + mt * 16 + gr;
#pragma unroll
        for (int nt = 0; nt < 4; nt++) {
            const int cbase = n0 + nbw + nt * 8;
            const float2 bi = *(const float2*)(bias + cbase + 2 * ck);
            if (SPLIT) {
                // store k-interleaved + tf32-rounded (consumed by attention)
                const int h = cbase >> 6;
                const int dp = (cbase & 63) + p0;
                const int b0_ = row >> 11, s0 = row & 2047;
                const int row1 = row + 8;
                const int b1_ = row1 >> 11, s1 = row1 & 2047;
                float* d0 = &C[(((size_t)(b0_ * Hh + h)) * Ss + s0) * HDd + dp];
                float* d1 = &C[(((size_t)(b1_ * Hh + h)) * Ss + s1) * HDd + dp];
                d0[0] = to_tf32f(acc[mt][nt][0] + bi.x);
                d0[2] = to_tf32f(acc[mt][nt][1] + bi.y);
                d1[0] = to_tf32f(acc[mt][nt][2] + bi.x);
                d1[2] = to_tf32f(acc[mt][nt][3] + bi.y);
            } else {
                const int col = cbase + 2 * ck;
                float2 v0, v1;
                v0.x = acc[mt][nt][0] + bi.x; v0.y = acc[mt][nt][1] + bi.y;
                v1.x = acc[mt][nt][2] + bi.x; v1.y = acc[mt][nt][3] + bi.y;
                *(float2*)&C[(size_t)row * Dd + col] = v0;
                *(float2*)&C[(size_t)(row + 8) * Dd + col] = v1;
            }
        }
    }
}

__global__ __launch_bounds__(256, 2) void gemm_qkv_mma_kernel(
    const float* __restrict__ bq, const float* __restrict__ bk,
    const float* __restrict__ bv)
{
    const int z = blockIdx.z;
    const float* A    = g_scratch + OFF_AR + (size_t)z * QKV_ELEMS;
    const float* bias = (z == 0) ? bq : ((z == 1) ? bk : bv);
    const float* BT   = g_scratch + OFF_WT + (size_t)z * WT_ELEMS;
    float* C = g_scratch + (size_t)z * QKV_ELEMS;
    gemm_mma<1>(A, BT, bias, C);
}

__global__ __launch_bounds__(256, 2) void gemm_out_mma_kernel(
    const float* __restrict__ bo, float* __restrict__ out)
{
    const float* A  = g_scratch + OFF_CAT;                 // concat (interleaved)
    const float* BT = g_scratch + OFF_WT + 3ull * WT_ELEMS;
    gemm_mma<0>(A, BT, bo, out);
}

// ---------------------------------------------------------------------------
// MMA flash attention (tf32), causal. q/k/v head-dim is 8-group interleaved ->
// LDS.64 fragment loads (stride 72 = conflict-free). O written interleaved,
// matching the out-GEMM's A convention. log2-domain softmax, 3 CTAs/SM.
// ---------------------------------------------------------------------------
#define AST 72                        // sQ/sK/sV row stride (floats)
#define SK_OFF (128*AST)              // 9216
#define SK_BUF (32*AST)               // 2304
#define SV_OFF (SK_OFF + 2*SK_BUF)    // 13824
#define SV_BUF (32*AST)               // 2304
#define ATTN_SMEM_BYTES ((SV_OFF + 2*SV_BUF) * 4)   // 73728

__global__ __launch_bounds__(128, 3) void attn_mma_kernel()
{
    extern __shared__ float sm[];
    const int bx = blockIdx.x;
    const int qt = 15 - (bx >> 5);         // heavy CTAs launch first
    const int bh = bx & 31;
    const int q0 = qt * 128;
    const int tid = threadIdx.x;
    const int wq = tid >> 5, lane = tid & 31;
    const int gr = lane >> 2, tg = lane & 3;

    const float* Qp = g_scratch + (size_t)bh * (Ss * HDd) + (size_t)q0 * HDd;
    const float* Kp = g_scratch + (size_t)QKV_ELEMS     + (size_t)bh * (Ss * HDd);
    const float* Vp = g_scratch + 2ull * QKV_ELEMS      + (size_t)bh * (Ss * HDd);

    const uint32_t smb = smem_u32(sm);

#define KISSUE(buf, t0) do { \
        _Pragma("unroll") \
        for (int j_ = 0; j_ < 4; j_++) { \
            const int f_ = tid + j_ * 128; \
            const int r_ = f_ >> 4; const int c_ = (f_ & 15) * 4; \
            CP16(smb + (uint32_t)(SK_OFF + (buf)*SK_BUF + r_*AST + c_) * 4, \
                 Kp + (size_t)((t0) + r_) * HDd + c_); \
            CP16(smb + (uint32_t)(SV_OFF + (buf)*SV_BUF + r_*AST + c_) * 4, \
                 Vp + (size_t)((t0) + r_) * HDd + c_); \
        } \
        CPCOMMIT(); \
    } while (0)

    KISSUE(0, 0);

    // stage Q, pre-scaled by log2(e)/8, re-rounded rna to tf32
    const float qsc = 0.18033688011112042f;   // 1.4426950408889634 / 8
#pragma unroll
    for (int i = 0; i < 16; i++) {
        const int f = tid + i * 128;            // 0..2047
        const int r = f >> 4, c = (f & 15) * 4;
        float4 qv = *(const float4*)(Qp + (size_t)r * HDd + c);
        qv.x = to_tf32f(qv.x * qsc); qv.y = to_tf32f(qv.y * qsc);
        qv.z = to_tf32f(qv.z * qsc); qv.w = to_tf32f(qv.w * qsc);
        *(float4*)(sm + r * AST + c) = qv;
    }

    float Of[2][8][4];
#pragma unroll
    for (int mt = 0; mt < 2; mt++)
#pragma unroll
        for (int nt = 0; nt < 8; nt++)
#pragma unroll
            for (int r = 0; r < 4; r++) Of[mt][nt][r] = 0.f;
    float m_[2][2] = {{-1e30f, -1e30f}, {-1e30f, -1e30f}};
    float l_[2][2] = {{0.f, 0.f}, {0.f, 0.f}};

    const int ntiles = qt * 4 + 4;
    const int my_last = qt * 4 + wq;       // this warp's diagonal tile

    for (int it = 0; it < ntiles; it++) {
        CPWAIT(0);
        __syncthreads();
        if (it + 1 < ntiles) KISSUE((it + 1) & 1, (it + 1) * 32);

        if (it <= my_last) {
            const uint32_t* K_ = (const uint32_t*)(sm + SK_OFF + (it & 1) * SK_BUF);
            const uint32_t* Q_ = (const uint32_t*)sm;
            float Sc[2][4][4];
#pragma unroll
            for (int mt = 0; mt < 2; mt++)
#pragma unroll
                for (int nt = 0; nt < 4; nt++)
#pragma unroll
                    for (int r = 0; r < 4; r++) Sc[mt][nt][r] = 0.f;

#pragma unroll
            for (int kt = 0; kt < 8; kt++) {
                const int ko = kt * 8 + 2 * tg;
                uint2 bk[4];
#pragma unroll
                for (int nt = 0; nt < 4; nt++)
                    bk[nt] = *(const uint2*)&K_[(nt * 8 + gr) * AST + ko];
#pragma unroll
                for (int mt = 0; mt < 2; mt++) {
                    const int r = wq * 32 + mt * 16 + gr;
                    const uint2 a01 = *(const uint2*)&Q_[r * AST + ko];
                    const uint2 a23 = *(const uint2*)&Q_[(r + 8) * AST + ko];
                    uint32_t aq[4] = {a01.x, a23.x, a01.y, a23.y};
#pragma unroll
                    for (int nt = 0; nt < 4; nt++)
                        mma_tf32(Sc[mt][nt], aq, (const uint32_t*)&bk[nt]);
                }
            }

            if (it == my_last) {           // diagonal tile: causal mask
                const int t0k = it * 32;
#pragma unroll
                for (int mt = 0; mt < 2; mt++) {
                    const int r0 = q0 + wq * 32 + mt * 16 + gr;
#pragma unroll
                    for (int nt = 0; nt < 4; nt++) {
                        const int key = t0k + nt * 8 + 2 * tg;
                        if (key > r0)        Sc[mt][nt][0] = -1e30f;
                        if (key + 1 > r0)    Sc[mt][nt][1] = -1e30f;
                        if (key > r0 + 8)    Sc[mt][nt][2] = -1e30f;
                        if (key + 1 > r0 + 8) Sc[mt][nt][3] = -1e30f;
                    }
                }
            }

            // online softmax (log2 domain)
#pragma unroll
            for (int mt = 0; mt < 2; mt++)
#pragma unroll
                for (int h = 0; h < 2; h++) {
                    float tm = fmaxf(fmaxf(Sc[mt][0][2*h], Sc[mt][0][2*h+1]),
                                     fmaxf(Sc[mt][1][2*h], Sc[mt][1][2*h+1]));
                    tm = fmaxf(tm, fmaxf(fmaxf(Sc[mt][2][2*h], Sc[mt][2][2*h+1]),
                                         fmaxf(Sc[mt][3][2*h], Sc[mt][3][2*h+1])));
                    tm = fmaxf(tm, __shfl_xor_sync(0xffffffffu, tm, 1));
                    tm = fmaxf(tm, __shfl_xor_sync(0xffffffffu, tm, 2));
                    const float mnew = fmaxf(m_[mt][h], tm);
                    const float corr = exp2f(m_[mt][h] - mnew);
                    m_[mt][h] = mnew;
                    l_[mt][h] *= corr;
#pragma unroll
                    for (int nt = 0; nt < 8; nt++) {
                        Of[mt][nt][2*h]     *= corr;
                        Of[mt][nt][2*h + 1] *= corr;
                    }
                }

            float rs[2][2] = {{0.f, 0.f}, {0.f, 0.f}};
#pragma unroll
            for (int mt = 0; mt < 2; mt++)
#pragma unroll
                for (int nt = 0; nt < 4; nt++) {
                    const float p0 = exp2f(Sc[mt][nt][0] - m_[mt][0]);
                    const float p1 = exp2f(Sc[mt][nt][1] - m_[mt][0]);
                    const float p2 = exp2f(Sc[mt][nt][2] - m_[mt][1]);
                    const float p3 = exp2f(Sc[mt][nt][3] - m_[mt][1]);
                    rs[mt][0] += p0 + p1;
                    rs[mt][1] += p2 + p3;
                    Sc[mt][nt][0] = to_tf32f(p0);
                    Sc[mt][nt][1] = to_tf32f(p1);
                    Sc[mt][nt][2] = to_tf32f(p2);
                    Sc[mt][nt][3] = to_tf32f(p3);
                }
#pragma unroll
            for (int mt = 0; mt < 2; mt++)
#pragma unroll
                for (int h = 0; h < 2; h++) {
                    float r = rs[mt][h];
                    r += __shfl_xor_sync(0xffffffffu, r, 1);
                    r += __shfl_xor_sync(0xffffffffu, r, 2);
                    l_[mt][h] += r;
                }

            // P @ V  (V head-dim interleaved; O inherits the interleave)
            const uint32_t* V_ = (const uint32_t*)(sm + SV_OFF + (it & 1) * SV_BUF);
            const int qb = lane & 28;
#pragma unroll
            for (int kt = 0; kt < 4; kt++) {
                uint32_t ap[2][4];
#pragma unroll
                for (int mt = 0; mt < 2; mt++) {
                    const int s0 = qb + (tg >> 1);
                    const float x0 = __shfl_sync(0xffffffffu, Sc[mt][kt][0], s0);
                    const float x1 = __shfl_sync(0xffffffffu, Sc[mt][kt][1], s0);
                    const float x2 = __shfl_sync(0xffffffffu, Sc[mt][kt][2], s0);
                    const float x3 = __shfl_sync(0xffffffffu, Sc[mt][kt][3], s0);
                    const float y0 = __shfl_sync(0xffffffffu, Sc[mt][kt][0], s0 + 2);
                    const float y1 = __shfl_sync(0xffffffffu, Sc[mt][kt][1], s0 + 2);
                    const float y2 = __shfl_sync(0xffffffffu, Sc[mt][kt][2], s0 + 2);
                    const float y3 = __shfl_sync(0xffffffffu, Sc[mt][kt][3], s0 + 2);
                    ap[mt][0] = __float_as_uint((tg & 1) ? x1 : x0);
                    ap[mt][1] = __float_as_uint((tg & 1) ? x3 : x2);
                    ap[mt][2] = __float_as_uint((tg & 1) ? y1 : y0);
                    ap[mt][3] = __float_as_uint((tg & 1) ? y3 : y2);
                }
#pragma unroll
                for (int ntd = 0; ntd < 8; ntd++) {
                    uint32_t bv[2];
                    bv[0] = V_[(kt * 8 + tg) * AST + ntd * 8 + gr];
                    bv[1] = V_[(kt * 8 + tg + 4) * AST + ntd * 8 + gr];
                    mma_tf32(Of[0][ntd], ap[0], bv);
                    mma_tf32(Of[1][ntd], ap[1], bv);
                }
            }
        }
    }
#undef KISSUE

    // epilogue -> concat (interleaved convention, tf32-rounded)
    float inv[2][2];
#pragma unroll
    for (int mt = 0; mt < 2; mt++) {
        inv[mt][0] = 1.f / l_[mt][0];
        inv[mt][1] = 1.f / l_[mt][1];
    }
    const int b_ = bh >> 4, h_ = bh & 15;
#pragma unroll
    for (int mt = 0; mt < 2; mt++) {
        const int r0 = q0 + wq * 32 + mt * 16 + gr;
        float* o0 = g_scratch + OFF_CAT + ((size_t)(b_ * Ss + r0)) * Dd + h_ * 64;
        float* o1 = g_scratch + OFF_CAT + ((size_t)(b_ * Ss + r0 + 8)) * Dd + h_ * 64;
#pragma unroll
        for (int ntd = 0; ntd < 8; ntd++) {
            const int col = ntd * 8 + 2 * tg;
            float2 v0, v1;
            v0.x = to_tf32f(Of[mt][ntd][0] * inv[mt][0]);
            v0.y = to_tf32f(Of[mt][ntd][1] * inv[mt][0]);
            v1.x = to_tf32f(Of[mt][ntd][2] * inv[mt][1]);
            v1.y = to_tf32f(Of[mt][ntd][3] * inv[mt][1]);
            *(float2*)(o0 + col) = v0;
            *(float2*)(o1 + col) = v1;
        }
    }
}

// ---------------------------------------------------------------------------
extern "C" void kernel_launch(void* const* d_in, const int* in_sizes, int n_in,
                              void* d_out, int out_size)
{
    const float* q_in = (const float*)d_in[0];
    const float* k_in = (const float*)d_in[1];
    const float* v_in = (const float*)d_in[2];
    const float* Wq   = (const float*)d_in[3];
    const float* bq   = (const float*)d_in[4];
    const float* Wk   = (const float*)d_in[5];
    const float* bk   = (const float*)d_in[6];
    const float* Wv   = (const float*)d_in[7];
    const float* bv   = (const float*)d_in[8];
    const float* Wo   = (const float*)d_in[9];
    const float* bo   = (const float*)d_in[10];
    float* out = (float*)d_out;

    cudaFuncSetAttribute(gemm_qkv_mma_kernel,
                         cudaFuncAttributeMaxDynamicSharedMemorySize, GEMM_SMEM_BYTES);
    cudaFuncSetAttribute(gemm_out_mma_kernel,
                         cudaFuncAttributeMaxDynamicSharedMemorySize, GEMM_SMEM_BYTES);
    cudaFuncSetAttribute(attn_mma_kernel,
                         cudaFuncAttributeMaxDynamicSharedMemorySize, ATTN_SMEM_BYTES);

    round_inputs_kernel<<<dim3(QKV_ELEMS / 2048, 3), 256>>>(q_in, k_in, v_in);
    transpose_w_kernel<<<dim3(32, 32, 4), dim3(32, 8)>>>(Wq, Wk, Wv, Wo);

    gemm_qkv_mma_kernel<<<dim3(8, 32, 3), 256, GEMM_SMEM_BYTES>>>(bq, bk, bv);

    attn_mma_kernel<<<512, 128, ATTN_SMEM_BYTES>>>();

    gemm_out_mma_kernel<<<dim3(8, 32), 256, GEMM_SMEM_BYTES>>>(bo, out);
}

// round 9
// speedup vs baseline: 3.9933x; 1.0589x over previous
#include <cuda_runtime.h>
#include <cstdint>

#define Bb 2
#define Ss 2048
#define Dd 1024
#define Hh 16
#define HDd 64
#define QKV_ELEMS (Bb*Hh*Ss*HDd)   // 4194304
#define WT_ELEMS (Dd*Dd)           // 1048576

#define OFF_CAT (3ull*QKV_ELEMS)
#define OFF_WT  (4ull*QKV_ELEMS)
#define OFF_AR  (4ull*QKV_ELEMS + 4ull*WT_ELEMS)

// q,k,v,concat, WT x4, rounded inputs x3   (k-dims stored 8-group interleaved)
static __device__ float g_scratch[7ull*QKV_ELEMS + 4ull*WT_ELEMS];

// ---------------------------------------------------------------------------
__device__ __forceinline__ uint32_t smem_u32(const void* p) {
    uint32_t a;
    asm("{ .reg .u64 t; cvta.to.shared.u64 t, %1; cvt.u32.u64 %0, t; }"
        : "=r"(a) : "l"(p));
    return a;
}
__device__ __forceinline__ float to_tf32f(float x) {
    uint32_t y; asm("cvt.rna.tf32.f32 %0, %1;" : "=r"(y) : "f"(x));
    return __uint_as_float(y);
}
__device__ __forceinline__ void mma_tf32(float* c, const uint32_t* a, const uint32_t* b) {
    asm volatile(
        "mma.sync.aligned.m16n8k8.row.col.f32.tf32.tf32.f32 "
        "{%0,%1,%2,%3}, {%4,%5,%6,%7}, {%8,%9}, {%0,%1,%2,%3};"
        : "+f"(c[0]), "+f"(c[1]), "+f"(c[2]), "+f"(c[3])
        : "r"(a[0]), "r"(a[1]), "r"(a[2]), "r"(a[3]), "r"(b[0]), "r"(b[1]));
}
#define CP16(smem_addr, gptr) \
    asm volatile("cp.async.ca.shared.global [%0], [%1], 16;" \
                 :: "r"(smem_addr), "l"(gptr) : "memory")
#define CPCOMMIT() asm volatile("cp.async.commit_group;" ::: "memory")
#define CPWAIT(N)  asm volatile("cp.async.wait_group %0;" :: "n"(N) : "memory")

// ---------------------------------------------------------------------------
// Prep: round to tf32 + interleave k within 8-groups: pos p holds col (p>>1)+(p&1)*4
// ---------------------------------------------------------------------------
__global__ __launch_bounds__(256) void round_inputs_kernel(
    const float* __restrict__ q, const float* __restrict__ k,
    const float* __restrict__ v)
{
    const int z = blockIdx.y;
    const float* in = (z == 0) ? q : ((z == 1) ? k : v);
    float* out = g_scratch + OFF_AR + (size_t)z * QKV_ELEMS;
    const size_t i = ((size_t)blockIdx.x * 256 + threadIdx.x) * 8;
    float4 lo = *(const float4*)(in + i);
    float4 hi = *(const float4*)(in + i + 4);
    float4 o0, o1;
    o0.x = to_tf32f(lo.x); o0.y = to_tf32f(hi.x);
    o0.z = to_tf32f(lo.y); o0.w = to_tf32f(hi.y);
    o1.x = to_tf32f(lo.z); o1.y = to_tf32f(hi.z);
    o1.z = to_tf32f(lo.w); o1.w = to_tf32f(hi.w);
    *(float4*)(out + i)     = o0;
    *(float4*)(out + i + 4) = o1;
}

// Weight transpose + round + k-interleave: WT[n][pos(k)] = tf32(W[k][n])
__global__ __launch_bounds__(256) void transpose_w_kernel(
    const float* __restrict__ Wq, const float* __restrict__ Wk,
    const float* __restrict__ Wv, const float* __restrict__ Wo)
{
    __shared__ float t[32][33];
    const int z = blockIdx.z;
    const float* W = (z == 0) ? Wq : ((z == 1) ? Wk : ((z == 2) ? Wv : Wo));
    float* WT = g_scratch + OFF_WT + (size_t)z * WT_ELEMS;
    const int x0 = blockIdx.x * 32, y0 = blockIdx.y * 32;
    const int tx = threadIdx.x, ty = threadIdx.y;
#pragma unroll
    for (int j = 0; j < 32; j += 8)
        t[ty + j][tx] = W[(size_t)(y0 + ty + j) * Dd + x0 + tx];
    __syncthreads();
    // k-col y0+tx -> position within 8-group: pos(c)=2*(c&3)+(c>>2)
    const int kp = y0 + (tx & 24) + 2 * (tx & 3) + ((tx >> 2) & 1);
#pragma unroll
    for (int j = 0; j < 32; j += 8)
        WT[(size_t)(x0 + ty + j) * Dd + kp] = to_tf32f(t[tx][ty + j]);
}

// ---------------------------------------------------------------------------
// tf32 mma.sync GEMM, 5-stage cp.async pipeline, packed stride-16 tiles with
// per-row ks-group swap -> conflict-free LDS.64 fragment loads.
// A,BT pre-rounded + k-interleaved in gmem.
// ---------------------------------------------------------------------------
#define TILE_F (128 * 16)         // 2048 floats per matrix tile
#define STAGE_F (2 * TILE_F)      // 4096
#define NSTAGE 5
#define GEMM_SMEM_BYTES (NSTAGE * STAGE_F * 4)   // 81920

template<int SPLIT>
__device__ __forceinline__ void gemm_mma(const float* __restrict__ A,
                                         const float* __restrict__ BT,
                                         const float* __restrict__ bias,
                                         float* __restrict__ C)
{
    extern __shared__ float smf[];

    const int tid = threadIdx.x;
    const int wid = tid >> 5, lane = tid & 31;
    const int m0 = blockIdx.y * 128, n0 = blockIdx.x * 128;

    // loader: thread -> rows (row0, row0+64), 16B chunk c4 (of 4 per row)
    const int row0 = tid >> 2, c4 = tid & 3;
    const int swp = ((c4 >> 1) ^ ((row0 >> 1) & 1)) << 3;
    const uint32_t so0 = (uint32_t)(row0 * 16 + swp + (c4 & 1) * 4) * 4;
    const uint32_t so1 = so0 + 64 * 16 * 4;   // (row0+64): same swap bit
    const float* gA0 = A  + (size_t)(m0 + row0) * Dd + c4 * 4;
    const float* gA1 = A  + (size_t)(m0 + row0 + 64) * Dd + c4 * 4;
    const float* gB0 = BT + (size_t)(n0 + row0) * Dd + c4 * 4;
    const float* gB1 = BT + (size_t)(n0 + row0 + 64) * Dd + c4 * 4;
    const uint32_t sbase = smem_u32(smf);

    const int wm = wid >> 2, wn = wid & 3;
    const int mbw = wm * 64, nbw = wn * 32;
    const int gr = lane >> 2, ck = lane & 3;

    float acc[4][4][4];
#pragma unroll
    for (int i = 0; i < 4; i++)
#pragma unroll
        for (int j = 0; j < 4; j++)
#pragma unroll
            for (int r = 0; r < 4; r++) acc[i][j][r] = 0.f;

#define GISSUE(buf, k0) do { \
        uint32_t a_ = sbase + (uint32_t)(buf) * (STAGE_F * 4); \
        uint32_t b_ = a_ + TILE_F * 4; \
        CP16(a_ + so0, gA0 + (k0)); CP16(a_ + so1, gA1 + (k0)); \
        CP16(b_ + so0, gB0 + (k0)); CP16(b_ + so1, gB1 + (k0)); \
        CPCOMMIT(); \
    } while (0)

    GISSUE(0, 0); GISSUE(1, 16); GISSUE(2, 32); GISSUE(3, 48);

    const int NIT = Dd / 16;   // 64
    const int swk = (gr >> 1) & 1;
    for (int it = 0; it < NIT; ++it) {
        CPWAIT(3);
        __syncthreads();
        if (it + 4 < NIT) GISSUE((it + 4) % NSTAGE, (it + 4) * 16);
        else CPCOMMIT();   // keep group count invariant (tail correctness)

        const uint32_t* SA = (const uint32_t*)(smf + (size_t)(it % NSTAGE) * STAGE_F);
        const uint32_t* SB = SA + TILE_F;
#pragma unroll
        for (int ks = 0; ks < 2; ks++) {
            const int ko = ((ks ^ swk) << 3) + 2 * ck;
            uint2 bfr[4];
#pragma unroll
            for (int nt = 0; nt < 4; nt++)
                bfr[nt] = *(const uint2*)&SB[(nbw + nt * 8 + gr) * 16 + ko];
#pragma unroll
            for (int mt = 0; mt < 4; mt++) {
                const int rb = (mbw + mt * 16 + gr) * 16 + ko;
                const uint2 a01 = *(const uint2*)&SA[rb];
                const uint2 a23 = *(const uint2*)&SA[rb + 8 * 16];
                uint32_t af[4] = {a01.x, a23.x, a01.y, a23.y};
#pragma unroll
                for (int nt = 0; nt < 4; nt++)
                    mma_tf32(acc[mt][nt], af, (const uint32_t*)&bfr[nt]);
            }
        }
    }
#undef GISSUE

    // epilogue with bias
    const int p0 = ((ck & 1) << 2) + (ck >> 1);   // pos(2ck); pos(2ck+1)=p0+2
#pragma unroll
    for (int mt = 0; mt < 4; mt++) {
        const int row = m0 + mbw + mt * 16 + gr;
#pragma unroll
        for (int nt = 0; nt < 4; nt++) {
            const int cbase = n0 + nbw + nt * 8;
            const float2 bi = *(const float2*)(bias + cbase + 2 * ck);
            if (SPLIT) {
                // store k-interleaved + tf32-rounded (consumed by attention)
                const int h = cbase >> 6;
                const int dp = (cbase & 63) + p0;
                const int b0_ = row >> 11, s0 = row & 2047;
                const int row1 = row + 8;
                const int b1_ = row1 >> 11, s1 = row1 & 2047;
                float* d0 = &C[(((size_t)(b0_ * Hh + h)) * Ss + s0) * HDd + dp];
                float* d1 = &C[(((size_t)(b1_ * Hh + h)) * Ss + s1) * HDd + dp];
                d0[0] = to_tf32f(acc[mt][nt][0] + bi.x);
                d0[2] = to_tf32f(acc[mt][nt][1] + bi.y);
                d1[0] = to_tf32f(acc[mt][nt][2] + bi.x);
                d1[2] = to_tf32f(acc[mt][nt][3] + bi.y);
            } else {
                const int col = cbase + 2 * ck;
                float2 v0, v1;
                v0.x = acc[mt][nt][0] + bi.x; v0.y = acc[mt][nt][1] + bi.y;
                v1.x = acc[mt][nt][2] + bi.x; v1.y = acc[mt][nt][3] + bi.y;
                *(float2*)&C[(size_t)row * Dd + col] = v0;
                *(float2*)&C[(size_t)(row + 8) * Dd + col] = v1;
            }
        }
    }
}

__global__ __launch_bounds__(256, 2) void gemm_qkv_mma_kernel(
    const float* __restrict__ bq, const float* __restrict__ bk,
    const float* __restrict__ bv)
{
    const int z = blockIdx.z;
    const float* A    = g_scratch + OFF_AR + (size_t)z * QKV_ELEMS;
    const float* bias = (z == 0) ? bq : ((z == 1) ? bk : bv);
    const float* BT   = g_scratch + OFF_WT + (size_t)z * WT_ELEMS;
    float* C = g_scratch + (size_t)z * QKV_ELEMS;
    gemm_mma<1>(A, BT, bias, C);
}

__global__ __launch_bounds__(256, 2) void gemm_out_mma_kernel(
    const float* __restrict__ bo, float* __restrict__ out)
{
    const float* A  = g_scratch + OFF_CAT;                 // concat (interleaved)
    const float* BT = g_scratch + OFF_WT + 3ull * WT_ELEMS;
    gemm_mma<0>(A, BT, bo, out);
}

// ---------------------------------------------------------------------------
// MMA flash attention (tf32), causal, intra-warp software-pipelined:
// QK of tile i+1 overlaps softmax+PV of tile i. K double-, V triple-buffered.
// q/k/v head-dim 8-group interleaved -> LDS.64 frags. log2 softmax. 2 CTAs/SM.
// ---------------------------------------------------------------------------
#define AST 72                        // sQ/sK/sV row stride (floats)
#define SK_OFF (128*AST)              // 9216
#define SKB (32*AST)                  // 2304 (one 32-key tile)
#define SV_OFF (SK_OFF + 2*SKB)       // K double buffer
#define ATTN_SMEM_BYTES ((SV_OFF + 3*SKB) * 4)   // 82944

__global__ __launch_bounds__(128, 2) void attn_mma_kernel()
{
    extern __shared__ float sm[];
    const int bx = blockIdx.x;
    const int qt = 15 - (bx >> 5);         // heavy CTAs launch first
    const int bh = bx & 31;
    const int q0 = qt * 128;
    const int tid = threadIdx.x;
    const int wq = tid >> 5, lane = tid & 31;
    const int gr = lane >> 2, tg = lane & 3;

    const float* Qp = g_scratch + (size_t)bh * (Ss * HDd) + (size_t)q0 * HDd;
    const float* Kp = g_scratch + (size_t)QKV_ELEMS     + (size_t)bh * (Ss * HDd);
    const float* Vp = g_scratch + 2ull * QKV_ELEMS      + (size_t)bh * (Ss * HDd);

    const uint32_t smb = smem_u32(sm);

#define KISSUE(kbuf, vbuf, t0) do { \
        _Pragma("unroll") \
        for (int j_ = 0; j_ < 4; j_++) { \
            const int f_ = tid + j_ * 128; \
            const int r_ = f_ >> 4; const int c_ = (f_ & 15) * 4; \
            CP16(smb + (uint32_t)(SK_OFF + (kbuf)*SKB + r_*AST + c_) * 4, \
                 Kp + (size_t)((t0) + r_) * HDd + c_); \
            CP16(smb + (uint32_t)(SV_OFF + (vbuf)*SKB + r_*AST + c_) * 4, \
                 Vp + (size_t)((t0) + r_) * HDd + c_); \
        } \
        CPCOMMIT(); \
    } while (0)

// QK^T for one 32-key tile from K buffer kbuf into S[2][4][4]
#define QK_TILE(S, kbuf) do { \
        const uint32_t* K_ = (const uint32_t*)(sm + SK_OFF + (kbuf) * SKB); \
        const uint32_t* Q_ = (const uint32_t*)sm; \
        _Pragma("unroll") \
        for (int mt_ = 0; mt_ < 2; mt_++) \
            _Pragma("unroll") \
            for (int nt_ = 0; nt_ < 4; nt_++) \
                _Pragma("unroll") \
                for (int r_ = 0; r_ < 4; r_++) S[mt_][nt_][r_] = 0.f; \
        _Pragma("unroll") \
        for (int kt_ = 0; kt_ < 8; kt_++) { \
            const int ko_ = kt_ * 8 + 2 * tg; \
            uint2 bkf_[4]; \
            _Pragma("unroll") \
            for (int nt_ = 0; nt_ < 4; nt_++) \
                bkf_[nt_] = *(const uint2*)&K_[(nt_ * 8 + gr) * AST + ko_]; \
            _Pragma("unroll") \
            for (int mt_ = 0; mt_ < 2; mt_++) { \
                const int rr_ = wq * 32 + mt_ * 16 + gr; \
                const uint2 a01_ = *(const uint2*)&Q_[rr_ * AST + ko_]; \
                const uint2 a23_ = *(const uint2*)&Q_[(rr_ + 8) * AST + ko_]; \
                uint32_t aq_[4] = {a01_.x, a23_.x, a01_.y, a23_.y}; \
                _Pragma("unroll") \
                for (int nt_ = 0; nt_ < 4; nt_++) \
                    mma_tf32(S[mt_][nt_], aq_, (const uint32_t*)&bkf_[nt_]); \
            } \
        } \
    } while (0)

    KISSUE(0, 0, 0);

    // stage Q, pre-scaled by log2(e)/8, re-rounded rna to tf32
    const float qsc = 0.18033688011112042f;   // 1.4426950408889634 / 8
#pragma unroll
    for (int i = 0; i < 16; i++) {
        const int f = tid + i * 128;            // 0..2047
        const int r = f >> 4, c = (f & 15) * 4;
        float4 qv = *(const float4*)(Qp + (size_t)r * HDd + c);
        qv.x = to_tf32f(qv.x * qsc); qv.y = to_tf32f(qv.y * qsc);
        qv.z = to_tf32f(qv.z * qsc); qv.w = to_tf32f(qv.w * qsc);
        *(float4*)(sm + r * AST + c) = qv;
    }

    float Of[2][8][4];
#pragma unroll
    for (int mt = 0; mt < 2; mt++)
#pragma unroll
        for (int nt = 0; nt < 8; nt++)
#pragma unroll
            for (int r = 0; r < 4; r++) Of[mt][nt][r] = 0.f;
    float m_[2][2] = {{-1e30f, -1e30f}, {-1e30f, -1e30f}};
    float l_[2][2] = {{0.f, 0.f}, {0.f, 0.f}};
    float Sc[2][4][4], Sn[2][4][4];

    const int ntiles = qt * 4 + 4;         // >= 4
    const int my_last = qt * 4 + wq;       // this warp's diagonal tile

    // prologue: tile0 visible, issue tile1, compute QK(0)
    CPWAIT(0);
    __syncthreads();
    KISSUE(1, 1, 32);
    QK_TILE(Sc, 0);

    for (int it = 0; it < ntiles; it++) {
        CPWAIT(0);          // tile it+1 complete (my slices)
        __syncthreads();    // ...visible to all; everyone past tile it-1 reads
        if (it + 2 < ntiles) KISSUE((it + 2) & 1, (it + 2) % 3, (it + 2) * 32);

        // QK for next tile (independent MMA stream, overlaps softmax below)
        const bool more = (it + 1 < ntiles) && (it + 1 <= my_last);
        if (more) QK_TILE(Sn, (it + 1) & 1);

        if (it <= my_last) {
            if (it == my_last) {           // diagonal tile: causal mask
                const int t0k = it * 32;
#pragma unroll
                for (int mt = 0; mt < 2; mt++) {
                    const int r0 = q0 + wq * 32 + mt * 16 + gr;
#pragma unroll
                    for (int nt = 0; nt < 4; nt++) {
                        const int key = t0k + nt * 8 + 2 * tg;
                        if (key > r0)        Sc[mt][nt][0] = -1e30f;
                        if (key + 1 > r0)    Sc[mt][nt][1] = -1e30f;
                        if (key > r0 + 8)    Sc[mt][nt][2] = -1e30f;
                        if (key + 1 > r0 + 8) Sc[mt][nt][3] = -1e30f;
                    }
                }
            }

            // online softmax (log2 domain)
#pragma unroll
            for (int mt = 0; mt < 2; mt++)
#pragma unroll
                for (int h = 0; h < 2; h++) {
                    float tm = fmaxf(fmaxf(Sc[mt][0][2*h], Sc[mt][0][2*h+1]),
                                     fmaxf(Sc[mt][1][2*h], Sc[mt][1][2*h+1]));
                    tm = fmaxf(tm, fmaxf(fmaxf(Sc[mt][2][2*h], Sc[mt][2][2*h+1]),
                                         fmaxf(Sc[mt][3][2*h], Sc[mt][3][2*h+1])));
                    tm = fmaxf(tm, __shfl_xor_sync(0xffffffffu, tm, 1));
                    tm = fmaxf(tm, __shfl_xor_sync(0xffffffffu, tm, 2));
                    const float mnew = fmaxf(m_[mt][h], tm);
                    const float corr = exp2f(m_[mt][h] - mnew);
                    m_[mt][h] = mnew;
                    l_[mt][h] *= corr;
#pragma unroll
                    for (int nt = 0; nt < 8; nt++) {
                        Of[mt][nt][2*h]     *= corr;
                        Of[mt][nt][2*h + 1] *= corr;
                    }
                }

            float rs[2][2] = {{0.f, 0.f}, {0.f, 0.f}};
#pragma unroll
            for (int mt = 0; mt < 2; mt++)
#pragma unroll
                for (int nt = 0; nt < 4; nt++) {
                    const float p0 = exp2f(Sc[mt][nt][0] - m_[mt][0]);
                    const float p1 = exp2f(Sc[mt][nt][1] - m_[mt][0]);
                    const float p2 = exp2f(Sc[mt][nt][2] - m_[mt][1]);
                    const float p3 = exp2f(Sc[mt][nt][3] - m_[mt][1]);
                    rs[mt][0] += p0 + p1;
                    rs[mt][1] += p2 + p3;
                    Sc[mt][nt][0] = to_tf32f(p0);
                    Sc[mt][nt][1] = to_tf32f(p1);
                    Sc[mt][nt][2] = to_tf32f(p2);
                    Sc[mt][nt][3] = to_tf32f(p3);
                }
#pragma unroll
            for (int mt = 0; mt < 2; mt++)
#pragma unroll
                for (int h = 0; h < 2; h++) {
                    float r = rs[mt][h];
                    r += __shfl_xor_sync(0xffffffffu, r, 1);
                    r += __shfl_xor_sync(0xffffffffu, r, 2);
                    l_[mt][h] += r;
                }

            // P @ V  (V head-dim interleaved; O inherits the interleave)
            const uint32_t* V_ = (const uint32_t*)(sm + SV_OFF + (it % 3) * SKB);
            const int qb = lane & 28;
#pragma unroll
            for (int kt = 0; kt < 4; kt++) {
                uint32_t ap[2][4];
#pragma unroll
                for (int mt = 0; mt < 2; mt++) {
                    const int s0 = qb + (tg >> 1);
                    const float x0 = __shfl_sync(0xffffffffu, Sc[mt][kt][0], s0);
                    const float x1 = __shfl_sync(0xffffffffu, Sc[mt][kt][1], s0);
                    const float x2 = __shfl_sync(0xffffffffu, Sc[mt][kt][2], s0);
                    const float x3 = __shfl_sync(0xffffffffu, Sc[mt][kt][3], s0);
                    const float y0 = __shfl_sync(0xffffffffu, Sc[mt][kt][0], s0 + 2);
                    const float y1 = __shfl_sync(0xffffffffu, Sc[mt][kt][1], s0 + 2);
                    const float y2 = __shfl_sync(0xffffffffu, Sc[mt][kt][2], s0 + 2);
                    const float y3 = __shfl_sync(0xffffffffu, Sc[mt][kt][3], s0 + 2);
                    ap[mt][0] = __float_as_uint((tg & 1) ? x1 : x0);
                    ap[mt][1] = __float_as_uint((tg & 1) ? x3 : x2);
                    ap[mt][2] = __float_as_uint((tg & 1) ? y1 : y0);
                    ap[mt][3] = __float_as_uint((tg & 1) ? y3 : y2);
                }
#pragma unroll
                for (int ntd = 0; ntd < 8; ntd++) {
                    uint32_t bv[2];
                    bv[0] = V_[(kt * 8 + tg) * AST + ntd * 8 + gr];
                    bv[1] = V_[(kt * 8 + tg + 4) * AST + ntd * 8 + gr];
                    mma_tf32(Of[0][ntd], ap[0], bv);
                    mma_tf32(Of[1][ntd], ap[1], bv);
                }
            }
        }

        // rotate score fragments
#pragma unroll
        for (int mt = 0; mt < 2; mt++)
#pragma unroll
            for (int nt = 0; nt < 4; nt++)
#pragma unroll
                for (int r = 0; r < 4; r++) Sc[mt][nt][r] = Sn[mt][nt][r];
    }
#undef KISSUE
#undef QK_TILE

    // epilogue -> concat (interleaved convention, tf32-rounded)
    float inv[2][2];
#pragma unroll
    for (int mt = 0; mt < 2; mt++) {
        inv[mt][0] = 1.f / l_[mt][0];
        inv[mt][1] = 1.f / l_[mt][1];
    }
    const int b_ = bh >> 4, h_ = bh & 15;
#pragma unroll
    for (int mt = 0; mt < 2; mt++) {
        const int r0 = q0 + wq * 32 + mt * 16 + gr;
        float* o0 = g_scratch + OFF_CAT + ((size_t)(b_ * Ss + r0)) * Dd + h_ * 64;
        float* o1 = g_scratch + OFF_CAT + ((size_t)(b_ * Ss + r0 + 8)) * Dd + h_ * 64;
#pragma unroll
        for (int ntd = 0; ntd < 8; ntd++) {
            const int col = ntd * 8 + 2 * tg;
            float2 v0, v1;
            v0.x = to_tf32f(Of[mt][ntd][0] * inv[mt][0]);
            v0.y = to_tf32f(Of[mt][ntd][1] * inv[mt][0]);
            v1.x = to_tf32f(Of[mt][ntd][2] * inv[mt][1]);
            v1.y = to_tf32f(Of[mt][ntd][3] * inv[mt][1]);
            *(float2*)(o0 + col) = v0;
            *(float2*)(o1 + col) = v1;
        }
    }
}

// ---------------------------------------------------------------------------
extern "C" void kernel_launch(void* const* d_in, const int* in_sizes, int n_in,
                              void* d_out, int out_size)
{
    const float* q_in = (const float*)d_in[0];
    const float* k_in = (const float*)d_in[1];
    const float* v_in = (const float*)d_in[2];
    const float* Wq   = (const float*)d_in[3];
    const float* bq   = (const float*)d_in[4];
    const float* Wk   = (const float*)d_in[5];
    const float* bk   = (const float*)d_in[6];
    const float* Wv   = (const float*)d_in[7];
    const float* bv   = (const float*)d_in[8];
    const float* Wo   = (const float*)d_in[9];
    const float* bo   = (const float*)d_in[10];
    float* out = (float*)d_out;

    cudaFuncSetAttribute(gemm_qkv_mma_kernel,
                         cudaFuncAttributeMaxDynamicSharedMemorySize, GEMM_SMEM_BYTES);
    cudaFuncSetAttribute(gemm_out_mma_kernel,
                         cudaFuncAttributeMaxDynamicSharedMemorySize, GEMM_SMEM_BYTES);
    cudaFuncSetAttribute(attn_mma_kernel,
                         cudaFuncAttributeMaxDynamicSharedMemorySize, ATTN_SMEM_BYTES);

    round_inputs_kernel<<<dim3(QKV_ELEMS / 2048, 3), 256>>>(q_in, k_in, v_in);
    transpose_w_kernel<<<dim3(32, 32, 4), dim3(32, 8)>>>(Wq, Wk, Wv, Wo);

    gemm_qkv_mma_kernel<<<dim3(8, 32, 3), 256, GEMM_SMEM_BYTES>>>(bq, bk, bv);

    attn_mma_kernel<<<512, 128, ATTN_SMEM_BYTES>>>();

    gemm_out_mma_kernel<<<dim3(8, 32), 256, GEMM_SMEM_BYTES>>>(bo, out);
}

// round 10
// speedup vs baseline: 4.0705x; 1.0193x over previous
#include <cuda_runtime.h>
#include <cstdint>

#define Bb 2
#define Ss 2048
#define Dd 1024
#define Hh 16
#define HDd 64
#define QKV_ELEMS (Bb*Hh*Ss*HDd)   // 4194304
#define WT_ELEMS (Dd*Dd)           // 1048576

#define OFF_CAT (3ull*QKV_ELEMS)
#define OFF_WT  (4ull*QKV_ELEMS)
#define OFF_AR  (4ull*QKV_ELEMS + 4ull*WT_ELEMS)

// q,k,v,concat, WT x4, rounded inputs x3   (k-dims stored 8-group interleaved)
static __device__ float g_scratch[7ull*QKV_ELEMS + 4ull*WT_ELEMS];

// ---------------------------------------------------------------------------
__device__ __forceinline__ uint32_t smem_u32(const void* p) {
    uint32_t a;
    asm("{ .reg .u64 t; cvta.to.shared.u64 t, %1; cvt.u32.u64 %0, t; }"
        : "=r"(a) : "l"(p));
    return a;
}
__device__ __forceinline__ float to_tf32f(float x) {
    uint32_t y; asm("cvt.rna.tf32.f32 %0, %1;" : "=r"(y) : "f"(x));
    return __uint_as_float(y);
}
__device__ __forceinline__ void mma_tf32(float* c, const uint32_t* a, const uint32_t* b) {
    asm volatile(
        "mma.sync.aligned.m16n8k8.row.col.f32.tf32.tf32.f32 "
        "{%0,%1,%2,%3}, {%4,%5,%6,%7}, {%8,%9}, {%0,%1,%2,%3};"
        : "+f"(c[0]), "+f"(c[1]), "+f"(c[2]), "+f"(c[3])
        : "r"(a[0]), "r"(a[1]), "r"(a[2]), "r"(a[3]), "r"(b[0]), "r"(b[1]));
}
#define CP16(smem_addr, gptr) \
    asm volatile("cp.async.ca.shared.global [%0], [%1], 16;" \
                 :: "r"(smem_addr), "l"(gptr) : "memory")
#define CPCOMMIT() asm volatile("cp.async.commit_group;" ::: "memory")
#define CPWAIT(N)  asm volatile("cp.async.wait_group %0;" :: "n"(N) : "memory")

// ---------------------------------------------------------------------------
// Prep: round to tf32 + interleave k within 8-groups: pos p holds col (p>>1)+(p&1)*4
// ---------------------------------------------------------------------------
__global__ __launch_bounds__(256) void round_inputs_kernel(
    const float* __restrict__ q, const float* __restrict__ k,
    const float* __restrict__ v)
{
    const int z = blockIdx.y;
    const float* in = (z == 0) ? q : ((z == 1) ? k : v);
    float* out = g_scratch + OFF_AR + (size_t)z * QKV_ELEMS;
    const size_t i = ((size_t)blockIdx.x * 256 + threadIdx.x) * 8;
    float4 lo = *(const float4*)(in + i);
    float4 hi = *(const float4*)(in + i + 4);
    float4 o0, o1;
    o0.x = to_tf32f(lo.x); o0.y = to_tf32f(hi.x);
    o0.z = to_tf32f(lo.y); o0.w = to_tf32f(hi.y);
    o1.x = to_tf32f(lo.z); o1.y = to_tf32f(hi.z);
    o1.z = to_tf32f(lo.w); o1.w = to_tf32f(hi.w);
    *(float4*)(out + i)     = o0;
    *(float4*)(out + i + 4) = o1;
}

// Weight transpose + round + k-interleave: WT[n][pos(k)] = tf32(W[k][n])
__global__ __launch_bounds__(256) void transpose_w_kernel(
    const float* __restrict__ Wq, const float* __restrict__ Wk,
    const float* __restrict__ Wv, const float* __restrict__ Wo)
{
    __shared__ float t[32][33];
    const int z = blockIdx.z;
    const float* W = (z == 0) ? Wq : ((z == 1) ? Wk : ((z == 2) ? Wv : Wo));
    float* WT = g_scratch + OFF_WT + (size_t)z * WT_ELEMS;
    const int x0 = blockIdx.x * 32, y0 = blockIdx.y * 32;
    const int tx = threadIdx.x, ty = threadIdx.y;
#pragma unroll
    for (int j = 0; j < 32; j += 8)
        t[ty + j][tx] = W[(size_t)(y0 + ty + j) * Dd + x0 + tx];
    __syncthreads();
    // k-col y0+tx -> position within 8-group: pos(c)=2*(c&3)+(c>>2)
    const int kp = y0 + (tx & 24) + 2 * (tx & 3) + ((tx >> 2) & 1);
#pragma unroll
    for (int j = 0; j < 32; j += 8)
        WT[(size_t)(x0 + ty + j) * Dd + kp] = to_tf32f(t[tx][ty + j]);
}

// ---------------------------------------------------------------------------
// tf32 mma.sync GEMM: CTA tile 256x128, warp tile 64x64 (8 warps, 4x2),
// 6-stage cp.async pipeline (5-ahead), packed stride-16 tiles with per-row
// ks-group swap -> conflict-free LDS.64 fragment loads. 1 CTA/SM.
// A,BT pre-rounded + k-interleaved in gmem.
// ---------------------------------------------------------------------------
#define GTA_F (256 * 16)          // A tile floats: 4096
#define GTB_F (128 * 16)          // B tile floats: 2048
#define GSTAGE_F (GTA_F + GTB_F)  // 6144
#define GNSTAGE 6
#define GEMM_SMEM_BYTES (GNSTAGE * GSTAGE_F * 4)   // 147456

template<int SPLIT>
__device__ __forceinline__ void gemm_mma(const float* __restrict__ A,
                                         const float* __restrict__ BT,
                                         const float* __restrict__ bias,
                                         float* __restrict__ C)
{
    extern __shared__ float smf[];

    const int tid = threadIdx.x;
    const int wid = tid >> 5, lane = tid & 31;
    const int m0 = blockIdx.y * 256, n0 = blockIdx.x * 128;

    // loader: thread -> A rows row0+{0,64,128,192}, B rows row0+{0,64}; chunk c4
    const int row0 = tid >> 2, c4 = tid & 3;
    const int swp = ((c4 >> 1) ^ ((row0 >> 1) & 1)) << 3;   // same for all +64k rows
    const uint32_t soBase = (uint32_t)(row0 * 16 + swp + (c4 & 1) * 4) * 4;
    const uint32_t soStep = 64 * 16 * 4;                     // +64 rows
    const float* gA0 = A  + (size_t)(m0 + row0) * Dd + c4 * 4;
    const float* gA1 = A  + (size_t)(m0 + row0 + 64) * Dd + c4 * 4;
    const float* gA2 = A  + (size_t)(m0 + row0 + 128) * Dd + c4 * 4;
    const float* gA3 = A  + (size_t)(m0 + row0 + 192) * Dd + c4 * 4;
    const float* gB0 = BT + (size_t)(n0 + row0) * Dd + c4 * 4;
    const float* gB1 = BT + (size_t)(n0 + row0 + 64) * Dd + c4 * 4;
    const uint32_t sbase = smem_u32(smf);

    // compute mapping: 8 warps = 4 (m) x 2 (n); warp tile 64x64
    const int wm = wid >> 1, wn = wid & 1;
    const int mbw = wm * 64, nbw = wn * 64;
    const int gr = lane >> 2, ck = lane & 3;

    float acc[4][8][4];
#pragma unroll
    for (int i = 0; i < 4; i++)
#pragma unroll
        for (int j = 0; j < 8; j++)
#pragma unroll
            for (int r = 0; r < 4; r++) acc[i][j][r] = 0.f;

#define GISSUE(buf, k0) do { \
        uint32_t a_ = sbase + (uint32_t)(buf) * (GSTAGE_F * 4); \
        uint32_t b_ = a_ + GTA_F * 4; \
        CP16(a_ + soBase,             gA0 + (k0)); \
        CP16(a_ + soBase + soStep,    gA1 + (k0)); \
        CP16(a_ + soBase + 2*soStep,  gA2 + (k0)); \
        CP16(a_ + soBase + 3*soStep,  gA3 + (k0)); \
        CP16(b_ + soBase,             gB0 + (k0)); \
        CP16(b_ + soBase + soStep,    gB1 + (k0)); \
        CPCOMMIT(); \
    } while (0)

    GISSUE(0, 0); GISSUE(1, 16); GISSUE(2, 32); GISSUE(3, 48); GISSUE(4, 64);

    const int NIT = Dd / 16;   // 64
    const int swk = (gr >> 1) & 1;
    for (int it = 0; it < NIT; ++it) {
        CPWAIT(4);
        __syncthreads();
        if (it + 5 < NIT) GISSUE((it + 5) % GNSTAGE, (it + 5) * 16);
        else CPCOMMIT();   // keep group count invariant (tail correctness)

        const uint32_t* SA = (const uint32_t*)(smf + (size_t)(it % GNSTAGE) * GSTAGE_F);
        const uint32_t* SB = SA + GTA_F;
#pragma unroll
        for (int ks = 0; ks < 2; ks++) {
            const int ko = ((ks ^ swk) << 3) + 2 * ck;
            uint2 bfr[8];
#pragma unroll
            for (int nt = 0; nt < 8; nt++)
                bfr[nt] = *(const uint2*)&SB[(nbw + nt * 8 + gr) * 16 + ko];
#pragma unroll
            for (int mt = 0; mt < 4; mt++) {
                const int rb = (mbw + mt * 16 + gr) * 16 + ko;
                const uint2 a01 = *(const uint2*)&SA[rb];
                const uint2 a23 = *(const uint2*)&SA[rb + 8 * 16];
                uint32_t af[4] = {a01.x, a23.x, a01.y, a23.y};
#pragma unroll
                for (int nt = 0; nt < 8; nt++)
                    mma_tf32(acc[mt][nt], af, (const uint32_t*)&bfr[nt]);
            }
        }
    }
#undef GISSUE

    // epilogue with bias
    const int p0 = ((ck & 1) << 2) + (ck >> 1);   // pos(2ck); pos(2ck+1)=p0+2
#pragma unroll
    for (int mt = 0; mt < 4; mt++) {
        const int row = m0 + mbw + mt * 16 + gr;
#pragma unroll
        for (int nt = 0; nt < 8; nt++) {
            const int cbase = n0 + nbw + nt * 8;
            const float2 bi = *(const float2*)(bias + cbase + 2 * ck);
            if (SPLIT) {
                // store k-interleaved + tf32-rounded (consumed by attention)
                const int h = cbase >> 6;
                const int dp = (cbase & 63) + p0;
                const int b0_ = row >> 11, s0 = row & 2047;
                const int row1 = row + 8;
                const int b1_ = row1 >> 11, s1 = row1 & 2047;
                float* d0 = &C[(((size_t)(b0_ * Hh + h)) * Ss + s0) * HDd + dp];
                float* d1 = &C[(((size_t)(b1_ * Hh + h)) * Ss + s1) * HDd + dp];
                d0[0] = to_tf32f(acc[mt][nt][0] + bi.x);
                d0[2] = to_tf32f(acc[mt][nt][1] + bi.y);
                d1[0] = to_tf32f(acc[mt][nt][2] + bi.x);
                d1[2] = to_tf32f(acc[mt][nt][3] + bi.y);
            } else {
                const int col = cbase + 2 * ck;
                float2 v0, v1;
                v0.x = acc[mt][nt][0] + bi.x; v0.y = acc[mt][nt][1] + bi.y;
                v1.x = acc[mt][nt][2] + bi.x; v1.y = acc[mt][nt][3] + bi.y;
                *(float2*)&C[(size_t)row * Dd + col] = v0;
                *(float2*)&C[(size_t)(row + 8) * Dd + col] = v1;
            }
        }
    }
}

__global__ __launch_bounds__(256, 1) void gemm_qkv_mma_kernel(
    const float* __restrict__ bq, const float* __restrict__ bk,
    const float* __restrict__ bv)
{
    const int z = blockIdx.z;
    const float* A    = g_scratch + OFF_AR + (size_t)z * QKV_ELEMS;
    const float* bias = (z == 0) ? bq : ((z == 1) ? bk : bv);
    const float* BT   = g_scratch + OFF_WT + (size_t)z * WT_ELEMS;
    float* C = g_scratch + (size_t)z * QKV_ELEMS;
    gemm_mma<1>(A, BT, bias, C);
}

__global__ __launch_bounds__(256, 1) void gemm_out_mma_kernel(
    const float* __restrict__ bo, float* __restrict__ out)
{
    const float* A  = g_scratch + OFF_CAT;                 // concat (interleaved)
    const float* BT = g_scratch + OFF_WT + 3ull * WT_ELEMS;
    gemm_mma<0>(A, BT, bo, out);
}

// ---------------------------------------------------------------------------
// MMA flash attention (tf32), causal, intra-warp software-pipelined:
// QK of tile i+1 overlaps softmax+PV of tile i. K double-, V triple-buffered.
// q/k/v head-dim 8-group interleaved -> LDS.64 frags. log2 softmax. 2 CTAs/SM.
// ---------------------------------------------------------------------------
#define AST 72                        // sQ/sK/sV row stride (floats)
#define SK_OFF (128*AST)              // 9216
#define SKB (32*AST)                  // 2304 (one 32-key tile)
#define SV_OFF (SK_OFF + 2*SKB)       // K double buffer
#define ATTN_SMEM_BYTES ((SV_OFF + 3*SKB) * 4)   // 82944

__global__ __launch_bounds__(128, 2) void attn_mma_kernel()
{
    extern __shared__ float sm[];
    const int bx = blockIdx.x;
    const int qt = 15 - (bx >> 5);         // heavy CTAs launch first
    const int bh = bx & 31;
    const int q0 = qt * 128;
    const int tid = threadIdx.x;
    const int wq = tid >> 5, lane = tid & 31;
    const int gr = lane >> 2, tg = lane & 3;

    const float* Qp = g_scratch + (size_t)bh * (Ss * HDd) + (size_t)q0 * HDd;
    const float* Kp = g_scratch + (size_t)QKV_ELEMS     + (size_t)bh * (Ss * HDd);
    const float* Vp = g_scratch + 2ull * QKV_ELEMS      + (size_t)bh * (Ss * HDd);

    const uint32_t smb = smem_u32(sm);

#define KISSUE(kbuf, vbuf, t0) do { \
        _Pragma("unroll") \
        for (int j_ = 0; j_ < 4; j_++) { \
            const int f_ = tid + j_ * 128; \
            const int r_ = f_ >> 4; const int c_ = (f_ & 15) * 4; \
            CP16(smb + (uint32_t)(SK_OFF + (kbuf)*SKB + r_*AST + c_) * 4, \
                 Kp + (size_t)((t0) + r_) * HDd + c_); \
            CP16(smb + (uint32_t)(SV_OFF + (vbuf)*SKB + r_*AST + c_) * 4, \
                 Vp + (size_t)((t0) + r_) * HDd + c_); \
        } \
        CPCOMMIT(); \
    } while (0)

// QK^T for one 32-key tile from K buffer kbuf into S[2][4][4]
#define QK_TILE(S, kbuf) do { \
        const uint32_t* K_ = (const uint32_t*)(sm + SK_OFF + (kbuf) * SKB); \
        const uint32_t* Q_ = (const uint32_t*)sm; \
        _Pragma("unroll") \
        for (int mt_ = 0; mt_ < 2; mt_++) \
            _Pragma("unroll") \
            for (int nt_ = 0; nt_ < 4; nt_++) \
                _Pragma("unroll") \
                for (int r_ = 0; r_ < 4; r_++) S[mt_][nt_][r_] = 0.f; \
        _Pragma("unroll") \
        for (int kt_ = 0; kt_ < 8; kt_++) { \
            const int ko_ = kt_ * 8 + 2 * tg; \
            uint2 bkf_[4]; \
            _Pragma("unroll") \
            for (int nt_ = 0; nt_ < 4; nt_++) \
                bkf_[nt_] = *(const uint2*)&K_[(nt_ * 8 + gr) * AST + ko_]; \
            _Pragma("unroll") \
            for (int mt_ = 0; mt_ < 2; mt_++) { \
                const int rr_ = wq * 32 + mt_ * 16 + gr; \
                const uint2 a01_ = *(const uint2*)&Q_[rr_ * AST + ko_]; \
                const uint2 a23_ = *(const uint2*)&Q_[(rr_ + 8) * AST + ko_]; \
                uint32_t aq_[4] = {a01_.x, a23_.x, a01_.y, a23_.y}; \
                _Pragma("unroll") \
                for (int nt_ = 0; nt_ < 4; nt_++) \
                    mma_tf32(S[mt_][nt_], aq_, (const uint32_t*)&bkf_[nt_]); \
            } \
        } \
    } while (0)

    KISSUE(0, 0, 0);

    // stage Q, pre-scaled by log2(e)/8, re-rounded rna to tf32
    const float qsc = 0.18033688011112042f;   // 1.4426950408889634 / 8
#pragma unroll
    for (int i = 0; i < 16; i++) {
        const int f = tid + i * 128;            // 0..2047
        const int r = f >> 4, c = (f & 15) * 4;
        float4 qv = *(const float4*)(Qp + (size_t)r * HDd + c);
        qv.x = to_tf32f(qv.x * qsc); qv.y = to_tf32f(qv.y * qsc);
        qv.z = to_tf32f(qv.z * qsc); qv.w = to_tf32f(qv.w * qsc);
        *(float4*)(sm + r * AST + c) = qv;
    }

    float Of[2][8][4];
#pragma unroll
    for (int mt = 0; mt < 2; mt++)
#pragma unroll
        for (int nt = 0; nt < 8; nt++)
#pragma unroll
            for (int r = 0; r < 4; r++) Of[mt][nt][r] = 0.f;
    float m_[2][2] = {{-1e30f, -1e30f}, {-1e30f, -1e30f}};
    float l_[2][2] = {{0.f, 0.f}, {0.f, 0.f}};
    float Sc[2][4][4], Sn[2][4][4];

    const int ntiles = qt * 4 + 4;         // >= 4
    const int my_last = qt * 4 + wq;       // this warp's diagonal tile

    // prologue: tile0 visible, issue tile1, compute QK(0)
    CPWAIT(0);
    __syncthreads();
    KISSUE(1, 1, 32);
    QK_TILE(Sc, 0);

    for (int it = 0; it < ntiles; it++) {
        CPWAIT(0);          // tile it+1 complete (my slices)
        __syncthreads();    // ...visible to all; everyone past tile it-1 reads
        if (it + 2 < ntiles) KISSUE((it + 2) & 1, (it + 2) % 3, (it + 2) * 32);

        // QK for next tile (independent MMA stream, overlaps softmax below)
        const bool more = (it + 1 < ntiles) && (it + 1 <= my_last);
        if (more) QK_TILE(Sn, (it + 1) & 1);

        if (it <= my_last) {
            if (it == my_last) {           // diagonal tile: causal mask
                const int t0k = it * 32;
#pragma unroll
                for (int mt = 0; mt < 2; mt++) {
                    const int r0 = q0 + wq * 32 + mt * 16 + gr;
#pragma unroll
                    for (int nt = 0; nt < 4; nt++) {
                        const int key = t0k + nt * 8 + 2 * tg;
                        if (key > r0)        Sc[mt][nt][0] = -1e30f;
                        if (key + 1 > r0)    Sc[mt][nt][1] = -1e30f;
                        if (key > r0 + 8)    Sc[mt][nt][2] = -1e30f;
                        if (key + 1 > r0 + 8) Sc[mt][nt][3] = -1e30f;
                    }
                }
            }

            // online softmax (log2 domain)
#pragma unroll
            for (int mt = 0; mt < 2; mt++)
#pragma unroll
                for (int h = 0; h < 2; h++) {
                    float tm = fmaxf(fmaxf(Sc[mt][0][2*h], Sc[mt][0][2*h+1]),
                                     fmaxf(Sc[mt][1][2*h], Sc[mt][1][2*h+1]));
                    tm = fmaxf(tm, fmaxf(fmaxf(Sc[mt][2][2*h], Sc[mt][2][2*h+1]),
                                         fmaxf(Sc[mt][3][2*h], Sc[mt][3][2*h+1])));
                    tm = fmaxf(tm, __shfl_xor_sync(0xffffffffu, tm, 1));
                    tm = fmaxf(tm, __shfl_xor_sync(0xffffffffu, tm, 2));
                    const float mnew = fmaxf(m_[mt][h], tm);
                    const float corr = exp2f(m_[mt][h] - mnew);
                    m_[mt][h] = mnew;
                    l_[mt][h] *= corr;
#pragma unroll
                    for (int nt = 0; nt < 8; nt++) {
                        Of[mt][nt][2*h]     *= corr;
                        Of[mt][nt][2*h + 1] *= corr;
                    }
                }

            float rs[2][2] = {{0.f, 0.f}, {0.f, 0.f}};
#pragma unroll
            for (int mt = 0; mt < 2; mt++)
#pragma unroll
                for (int nt = 0; nt < 4; nt++) {
                    const float p0 = exp2f(Sc[mt][nt][0] - m_[mt][0]);
                    const float p1 = exp2f(Sc[mt][nt][1] - m_[mt][0]);
                    const float p2 = exp2f(Sc[mt][nt][2] - m_[mt][1]);
                    const float p3 = exp2f(Sc[mt][nt][3] - m_[mt][1]);
                    rs[mt][0] += p0 + p1;
                    rs[mt][1] += p2 + p3;
                    Sc[mt][nt][0] = to_tf32f(p0);
                    Sc[mt][nt][1] = to_tf32f(p1);
                    Sc[mt][nt][2] = to_tf32f(p2);
                    Sc[mt][nt][3] = to_tf32f(p3);
                }
#pragma unroll
            for (int mt = 0; mt < 2; mt++)
#pragma unroll
                for (int h = 0; h < 2; h++) {
                    float r = rs[mt][h];
                    r += __shfl_xor_sync(0xffffffffu, r, 1);
                    r += __shfl_xor_sync(0xffffffffu, r, 2);
                    l_[mt][h] += r;
                }

            // P @ V  (V head-dim interleaved; O inherits the interleave)
            const uint32_t* V_ = (const uint32_t*)(sm + SV_OFF + (it % 3) * SKB);
            const int qb = lane & 28;
#pragma unroll
            for (int kt = 0; kt < 4; kt++) {
                uint32_t ap[2][4];
#pragma unroll
                for (int mt = 0; mt < 2; mt++) {
                    const int s0 = qb + (tg >> 1);
                    const float x0 = __shfl_sync(0xffffffffu, Sc[mt][kt][0], s0);
                    const float x1 = __shfl_sync(0xffffffffu, Sc[mt][kt][1], s0);
                    const float x2 = __shfl_sync(0xffffffffu, Sc[mt][kt][2], s0);
                    const float x3 = __shfl_sync(0xffffffffu, Sc[mt][kt][3], s0);
                    const float y0 = __shfl_sync(0xffffffffu, Sc[mt][kt][0], s0 + 2);
                    const float y1 = __shfl_sync(0xffffffffu, Sc[mt][kt][1], s0 + 2);
                    const float y2 = __shfl_sync(0xffffffffu, Sc[mt][kt][2], s0 + 2);
                    const float y3 = __shfl_sync(0xffffffffu, Sc[mt][kt][3], s0 + 2);
                    ap[mt][0] = __float_as_uint((tg & 1) ? x1 : x0);
                    ap[mt][1] = __float_as_uint((tg & 1) ? x3 : x2);
                    ap[mt][2] = __float_as_uint((tg & 1) ? y1 : y0);
                    ap[mt][3] = __float_as_uint((tg & 1) ? y3 : y2);
                }
#pragma unroll
                for (int ntd = 0; ntd < 8; ntd++) {
                    uint32_t bv[2];
                    bv[0] = V_[(kt * 8 + tg) * AST + ntd * 8 + gr];
                    bv[1] = V_[(kt * 8 + tg + 4) * AST + ntd * 8 + gr];
                    mma_tf32(Of[0][ntd], ap[0], bv);
                    mma_tf32(Of[1][ntd], ap[1], bv);
                }
            }
        }

        // rotate score fragments
#pragma unroll
        for (int mt = 0; mt < 2; mt++)
#pragma unroll
            for (int nt = 0; nt < 4; nt++)
#pragma unroll
                for (int r = 0; r < 4; r++) Sc[mt][nt][r] = Sn[mt][nt][r];
    }
#undef KISSUE
#undef QK_TILE

    // epilogue -> concat (interleaved convention, tf32-rounded)
    float inv[2][2];
#pragma unroll
    for (int mt = 0; mt < 2; mt++) {
        inv[mt][0] = 1.f / l_[mt][0];
        inv[mt][1] = 1.f / l_[mt][1];
    }
    const int b_ = bh >> 4, h_ = bh & 15;
#pragma unroll
    for (int mt = 0; mt < 2; mt++) {
        const int r0 = q0 + wq * 32 + mt * 16 + gr;
        float* o0 = g_scratch + OFF_CAT + ((size_t)(b_ * Ss + r0)) * Dd + h_ * 64;
        float* o1 = g_scratch + OFF_CAT + ((size_t)(b_ * Ss + r0 + 8)) * Dd + h_ * 64;
#pragma unroll
        for (int ntd = 0; ntd < 8; ntd++) {
            const int col = ntd * 8 + 2 * tg;
            float2 v0, v1;
            v0.x = to_tf32f(Of[mt][ntd][0] * inv[mt][0]);
            v0.y = to_tf32f(Of[mt][ntd][1] * inv[mt][0]);
            v1.x = to_tf32f(Of[mt][ntd][2] * inv[mt][1]);
            v1.y = to_tf32f(Of[mt][ntd][3] * inv[mt][1]);
            *(float2*)(o0 + col) = v0;
            *(float2*)(o1 + col) = v1;
        }
    }
}

// ---------------------------------------------------------------------------
extern "C" void kernel_launch(void* const* d_in, const int* in_sizes, int n_in,
                              void* d_out, int out_size)
{
    const float* q_in = (const float*)d_in[0];
    const float* k_in = (const float*)d_in[1];
    const float* v_in = (const float*)d_in[2];
    const float* Wq   = (const float*)d_in[3];
    const float* bq   = (const float*)d_in[4];
    const float* Wk   = (const float*)d_in[5];
    const float* bk   = (const float*)d_in[6];
    const float* Wv   = (const float*)d_in[7];
    const float* bv   = (const float*)d_in[8];
    const float* Wo   = (const float*)d_in[9];
    const float* bo   = (const float*)d_in[10];
    float* out = (float*)d_out;

    cudaFuncSetAttribute(gemm_qkv_mma_kernel,
                         cudaFuncAttributeMaxDynamicSharedMemorySize, GEMM_SMEM_BYTES);
    cudaFuncSetAttribute(gemm_out_mma_kernel,
                         cudaFuncAttributeMaxDynamicSharedMemorySize, GEMM_SMEM_BYTES);
    cudaFuncSetAttribute(attn_mma_kernel,
                         cudaFuncAttributeMaxDynamicSharedMemorySize, ATTN_SMEM_BYTES);

    round_inputs_kernel<<<dim3(QKV_ELEMS / 2048, 3), 256>>>(q_in, k_in, v_in);
    transpose_w_kernel<<<dim3(32, 32, 4), dim3(32, 8)>>>(Wq, Wk, Wv, Wo);

    gemm_qkv_mma_kernel<<<dim3(8, 16, 3), 256, GEMM_SMEM_BYTES>>>(bq, bk, bv);

    attn_mma_kernel<<<512, 128, ATTN_SMEM_BYTES>>>();

    gemm_out_mma_kernel<<<dim3(8, 16), 256, GEMM_SMEM_BYTES>>>(bo, out);
}

// round 12
// speedup vs baseline: 6.4645x; 1.5881x over previous
#include <cuda_runtime.h>
#include <cstdint>

#define Bb 2
#define Ss 2048
#define Dd 1024
#define Hh 16
#define HDd 64
#define QKV_ELEMS (Bb*Hh*Ss*HDd)   // 4194304 halves per tensor
#define QKV_U32 (QKV_ELEMS/2)      // 2097152 u32
#define WT_U32 ((Dd*Dd)/2)         // 524288 u32

// u32 regions: q,k,v (pair-interleaved half), Vp (key-pair packed), concat,
// WT x4 (interleaved half), rounded inputs x3 (interleaved half)
#define OFF_QKV 0ull
#define OFF_VP  (3ull*QKV_U32)
#define OFF_CAT (4ull*QKV_U32)
#define OFF_WT  (5ull*QKV_U32)
#define OFF_AR  (5ull*QKV_U32 + 4ull*WT_U32)

static __device__ uint32_t g_scratch[8ull*QKV_U32 + 4ull*WT_U32];

#define QSC 0.18033688011112042f   // log2(e)/8

// ---------------------------------------------------------------------------
__device__ __forceinline__ uint32_t smem_u32(const void* p) {
    uint32_t a;
    asm("{ .reg .u64 t; cvta.to.shared.u64 t, %1; cvt.u32.u64 %0, t; }"
        : "=r"(a) : "l"(p));
    return a;
}
// pack two floats to f16x2: lo -> low 16 bits (PTX: first src -> high half)
__device__ __forceinline__ uint32_t h2pack(float lo, float hi) {
    uint32_t d;
    asm("cvt.rn.f16x2.f32 %0, %1, %2;" : "=r"(d) : "f"(hi), "f"(lo));
    return d;
}
__device__ __forceinline__ void mma_f16(float* c, const uint32_t* a, const uint32_t* b) {
    asm volatile(
        "mma.sync.aligned.m16n8k16.row.col.f32.f16.f16.f32 "
        "{%0,%1,%2,%3}, {%4,%5,%6,%7}, {%8,%9}, {%0,%1,%2,%3};"
        : "+f"(c[0]), "+f"(c[1]), "+f"(c[2]), "+f"(c[3])
        : "r"(a[0]), "r"(a[1]), "r"(a[2]), "r"(a[3]), "r"(b[0]), "r"(b[1]));
}
#define CP16(smem_addr, gptr) \
    asm volatile("cp.async.ca.shared.global [%0], [%1], 16;" \
                 :: "r"(smem_addr), "l"(gptr) : "memory")
#define CPCOMMIT() asm volatile("cp.async.commit_group;" ::: "memory")
#define CPWAIT(N)  asm volatile("cp.async.wait_group %0;" :: "n"(N) : "memory")

// ---------------------------------------------------------------------------
// Prep: fp32 -> f16x2, pair-interleaved within each 16-half k-group:
// phys u32 pos p holds half-pair q=(p>>1)+(p&1)*4, i.e. halves (2q,2q+1).
// ---------------------------------------------------------------------------
__global__ __launch_bounds__(256) void round_inputs_kernel(
    const float* __restrict__ q, const float* __restrict__ k,
    const float* __restrict__ v)
{
    const int z = blockIdx.y;
    const float* in = (z == 0) ? q : ((z == 1) ? k : v);
    uint32_t* out = g_scratch + OFF_AR + (size_t)z * QKV_U32;
    const size_t i = ((size_t)blockIdx.x * 256 + threadIdx.x) * 16;
    float vv[16];
#pragma unroll
    for (int j = 0; j < 16; j += 4)
        *(float4*)&vv[j] = *(const float4*)(in + i + j);
    const size_t ob = i >> 1;
#pragma unroll
    for (int p = 0; p < 8; p++) {
        const int qq = (p >> 1) + (p & 1) * 4;
        out[ob + p] = h2pack(vv[2 * qq], vv[2 * qq + 1]);
    }
}

// Weight transpose + half + pair-interleave; Wq additionally scaled by QSC.
// t[r][c] = W[y0+r][x0+c]  (r = k-local, c = n-local)
// WT[n = x0+tx][k-pair block] must read t[k0][tx] (k-local row, n-local col).
__global__ __launch_bounds__(256) void transpose_w_kernel(
    const float* __restrict__ Wq, const float* __restrict__ Wk,
    const float* __restrict__ Wv, const float* __restrict__ Wo)
{
    __shared__ float t[32][33];
    const int z = blockIdx.z;
    const float* W = (z == 0) ? Wq : ((z == 1) ? Wk : ((z == 2) ? Wv : Wo));
    uint32_t* WT = g_scratch + OFF_WT + (size_t)z * WT_U32;
    const int x0 = blockIdx.x * 32, y0 = blockIdx.y * 32;
    const int tx = threadIdx.x, ty = threadIdx.y;
#pragma unroll
    for (int j = 0; j < 32; j += 8)
        t[ty + j][tx] = W[(size_t)(y0 + ty + j) * Dd + x0 + tx];
    __syncthreads();
    const float sc = (z == 0) ? QSC : 1.0f;
#pragma unroll
    for (int uu = 0; uu < 2; uu++) {
        const int u = ty * 2 + uu;               // u32 col within 16 (2 groups)
        const int g = u >> 3, p = u & 7;
        const int qq = (p >> 1) + (p & 1) * 4;
        const int k0 = g * 16 + 2 * qq;          // k-local half index
        const float a = t[k0][tx] * sc, b = t[k0 + 1][tx] * sc;
        WT[(size_t)(x0 + tx) * (Dd / 2) + (y0 >> 1) + u] = h2pack(a, b);
    }
}

// ---------------------------------------------------------------------------
// fp16 mma GEMM: CTA 256x128, warp 64x64 (8 warps 4x2), BK=32 halves (16 u32),
// 8-stage cp.async pipeline, packed stride-16-u32 tiles + ks-swap -> LDS.64.
// SPLIT=1: C half, [B,H,S,32u32] pair-interleaved along d; bias scaled by bsc.
// SPLIT=0: C float (d_out), bias added.
// ---------------------------------------------------------------------------
#define GTA_U (256 * 16)          // 4096 u32
#define GTB_U (128 * 16)          // 2048
#define GSTAGE_U (GTA_U + GTB_U)  // 6144
#define GNSTAGE 8
#define GEMM_SMEM_BYTES (GNSTAGE * GSTAGE_U * 4)   // 196608

template<int SPLIT>
__device__ __forceinline__ void gemm_mma(const uint32_t* __restrict__ A,
                                         const uint32_t* __restrict__ BT,
                                         const float* __restrict__ bias,
                                         float bsc, void* __restrict__ Cv)
{
    extern __shared__ uint32_t smu[];

    const int tid = threadIdx.x;
    const int wid = tid >> 5, lane = tid & 31;
    const int m0 = blockIdx.y * 256, n0 = blockIdx.x * 128;

    const int row0 = tid >> 2, c4 = tid & 3;
    const int swp = ((c4 >> 1) ^ ((row0 >> 1) & 1)) << 3;
    const uint32_t soBase = (uint32_t)(row0 * 16 + swp + (c4 & 1) * 4) * 4;
    const uint32_t soStep = 64 * 16 * 4;
    const uint32_t* gA0 = A  + (size_t)(m0 + row0) * 512 + c4 * 4;
    const uint32_t* gA1 = A  + (size_t)(m0 + row0 + 64) * 512 + c4 * 4;
    const uint32_t* gA2 = A  + (size_t)(m0 + row0 + 128) * 512 + c4 * 4;
    const uint32_t* gA3 = A  + (size_t)(m0 + row0 + 192) * 512 + c4 * 4;
    const uint32_t* gB0 = BT + (size_t)(n0 + row0) * 512 + c4 * 4;
    const uint32_t* gB1 = BT + (size_t)(n0 + row0 + 64) * 512 + c4 * 4;
    const uint32_t sbase = smem_u32(smu);

    const int wm = wid >> 1, wn = wid & 1;
    const int mbw = wm * 64, nbw = wn * 64;
    const int gr = lane >> 2, ck = lane & 3;

    float acc[4][8][4];
#pragma unroll
    for (int i = 0; i < 4; i++)
#pragma unroll
        for (int j = 0; j < 8; j++)
#pragma unroll
            for (int r = 0; r < 4; r++) acc[i][j][r] = 0.f;

#define GISSUE(buf, k0) do { \
        uint32_t a_ = sbase + (uint32_t)(buf) * (GSTAGE_U * 4); \
        uint32_t b_ = a_ + GTA_U * 4; \
        CP16(a_ + soBase,            gA0 + (k0)); \
        CP16(a_ + soBase + soStep,   gA1 + (k0)); \
        CP16(a_ + soBase + 2*soStep, gA2 + (k0)); \
        CP16(a_ + soBase + 3*soStep, gA3 + (k0)); \
        CP16(b_ + soBase,            gB0 + (k0)); \
        CP16(b_ + soBase + soStep,   gB1 + (k0)); \
        CPCOMMIT(); \
    } while (0)

    GISSUE(0, 0); GISSUE(1, 16); GISSUE(2, 32); GISSUE(3, 48);
    GISSUE(4, 64); GISSUE(5, 80); GISSUE(6, 96);

    const int NIT = 32;   // 1024 halves / 32 per iter
    const int swk = (gr >> 1) & 1;
    for (int it = 0; it < NIT; ++it) {
        CPWAIT(6);
        __syncthreads();
        if (it + 7 < NIT) GISSUE((it + 7) & 7, (it + 7) * 16);
        else CPCOMMIT();

        const uint32_t* SA = smu + (size_t)(it & 7) * GSTAGE_U;
        const uint32_t* SB = SA + GTA_U;
#pragma unroll
        for (int ks = 0; ks < 2; ks++) {
            const int ko = ((ks ^ swk) << 3) + 2 * ck;
            uint2 bfr[8];
#pragma unroll
            for (int nt = 0; nt < 8; nt++)
                bfr[nt] = *(const uint2*)&SB[(nbw + nt * 8 + gr) * 16 + ko];
#pragma unroll
            for (int mt = 0; mt < 4; mt++) {
                const int rb = (mbw + mt * 16 + gr) * 16 + ko;
                const uint2 a01 = *(const uint2*)&SA[rb];
                const uint2 a23 = *(const uint2*)&SA[rb + 8 * 16];
                uint32_t af[4] = {a01.x, a23.x, a01.y, a23.y};
#pragma unroll
                for (int nt = 0; nt < 8; nt++)
                    mma_f16(acc[mt][nt], af, (const uint32_t*)&bfr[nt]);
            }
        }
    }
#undef GISSUE

#pragma unroll
    for (int mt = 0; mt < 4; mt++) {
        const int row = m0 + mbw + mt * 16 + gr;
#pragma unroll
        for (int nt = 0; nt < 8; nt++) {
            const int cbase = n0 + nbw + nt * 8;
            const float2 bi = *(const float2*)(bias + cbase + 2 * ck);
            if (SPLIT) {
                uint32_t* C = (uint32_t*)Cv;
                const int h = cbase >> 6;
                const int dloc = cbase & 63;
                const int g = dloc >> 4;
                const int q_l = ((dloc >> 3) & 1) * 4 + ck;
                const int upos = g * 8 + 2 * (q_l & 3) + (q_l >> 2);
                const int b0_ = row >> 11, s0 = row & 2047;
                const int row1 = row + 8;
                const int b1_ = row1 >> 11, s1 = row1 & 2047;
                C[(((size_t)(b0_ * Hh + h)) * Ss + s0) * 32 + upos] =
                    h2pack(acc[mt][nt][0] + bi.x * bsc,
                           acc[mt][nt][1] + bi.y * bsc);
                C[(((size_t)(b1_ * Hh + h)) * Ss + s1) * 32 + upos] =
                    h2pack(acc[mt][nt][2] + bi.x * bsc,
                           acc[mt][nt][3] + bi.y * bsc);
            } else {
                float* C = (float*)Cv;
                const int col = cbase + 2 * ck;
                float2 v0, v1;
                v0.x = acc[mt][nt][0] + bi.x; v0.y = acc[mt][nt][1] + bi.y;
                v1.x = acc[mt][nt][2] + bi.x; v1.y = acc[mt][nt][3] + bi.y;
                *(float2*)&C[(size_t)row * Dd + col] = v0;
                *(float2*)&C[(size_t)(row + 8) * Dd + col] = v1;
            }
        }
    }
}

__global__ __launch_bounds__(256, 1) void gemm_qkv_mma_kernel(
    const float* __restrict__ bq, const float* __restrict__ bk,
    const float* __restrict__ bv)
{
    const int z = blockIdx.z;
    const uint32_t* A  = g_scratch + OFF_AR + (size_t)z * QKV_U32;
    const float* bias  = (z == 0) ? bq : ((z == 1) ? bk : bv);
    const uint32_t* BT = g_scratch + OFF_WT + (size_t)z * WT_U32;
    uint32_t* C = g_scratch + (size_t)z * QKV_U32;
    gemm_mma<1>(A, BT, bias, (z == 0) ? QSC : 1.0f, C);
}

__global__ __launch_bounds__(256, 1) void gemm_out_mma_kernel(
    const float* __restrict__ bo, float* __restrict__ out)
{
    const uint32_t* A  = g_scratch + OFF_CAT;
    const uint32_t* BT = g_scratch + OFF_WT + 3ull * WT_U32;
    gemm_mma<0>(A, BT, bo, 1.0f, out);
}

// ---------------------------------------------------------------------------
// V repack: [B,H,S,32u32] (d-interleaved halves) -> [B,H,S/2,64u32]
// where out[kp][d] = (V[2kp][d] lo | V[2kp+1][d] hi).
// ---------------------------------------------------------------------------
__global__ __launch_bounds__(256) void repack_v_kernel()
{
    const uint32_t* in = g_scratch + 2ull * QKV_U32;   // V
    uint32_t* out = g_scratch + OFF_VP;
    const size_t idx = (size_t)blockIdx.x * 256 + threadIdx.x;  // over (BHS/2)*32
    const size_t kp = idx >> 5;
    const int p = (int)(idx & 31);
    const uint32_t X = in[(2 * kp) * 32 + p];
    const uint32_t Y = in[(2 * kp + 1) * 32 + p];
    const int g = p >> 3, pp = p & 7;
    const int qq = (pp >> 1) + (pp & 1) * 4;
    const int d0 = g * 16 + 2 * qq;
    out[kp * 64 + d0]     = (X & 0xFFFFu) | (Y << 16);
    out[kp * 64 + d0 + 1] = (X >> 16) | (Y & 0xFFFF0000u);
}

// ---------------------------------------------------------------------------
// fp16 MMA flash attention, causal, intra-warp pipelined (QK i+1 overlaps
// softmax+PV of i). P fed to PV via direct f16x2 packing (no relayout SHFLs).
// K double-, V triple-buffered. Q pre-scaled by log2(e)/8 in the Q-GEMM.
// ---------------------------------------------------------------------------
#define QST 40                        // Q/K row stride (u32)
#define SQ_U (128 * QST)              // 5120
#define SK_OFF SQ_U
#define SKB2 (32 * QST)               // 1280
#define VST2 72
#define SV_OFF (SK_OFF + 2 * SKB2)    // 7680
#define SVB (16 * VST2)               // 1152
#define ATTN_SMEM_BYTES ((SV_OFF + 3 * SVB) * 4)   // 44544

__global__ __launch_bounds__(128, 2) void attn_mma_kernel()
{
    extern __shared__ uint32_t smu[];
    const int bx = blockIdx.x;
    const int qt = 15 - (bx >> 5);
    const int bh = bx & 31;
    const int q0 = qt * 128;
    const int tid = threadIdx.x;
    const int wq = tid >> 5, lane = tid & 31;
    const int gr = lane >> 2, tg = lane & 3;

    const uint32_t* Qp = g_scratch + ((size_t)bh * Ss + q0) * 32;
    const uint32_t* Kp = g_scratch + QKV_U32 + (size_t)bh * Ss * 32;
    const uint32_t* Vp = g_scratch + OFF_VP + (size_t)bh * (Ss / 2) * 64;

    const uint32_t smb = smem_u32(smu);

#define KISSUE(kbuf, vbuf, t0) do { \
        _Pragma("unroll") \
        for (int j_ = 0; j_ < 2; j_++) { \
            const int f_ = tid + j_ * 128; \
            const int rK = f_ >> 3; const int cK = (f_ & 7) * 4; \
            CP16(smb + (uint32_t)(SK_OFF + (kbuf)*SKB2 + rK*QST + cK) * 4, \
                 Kp + (size_t)((t0) + rK) * 32 + cK); \
            const int rV = f_ >> 4; const int cV = (f_ & 15) * 4; \
            CP16(smb + (uint32_t)(SV_OFF + (vbuf)*SVB + rV*VST2 + cV) * 4, \
                 Vp + (size_t)(((t0) >> 1) + rV) * 64 + cV); \
        } \
        CPCOMMIT(); \
    } while (0)

#define QK_TILE(S, kbuf) do { \
        const uint32_t* K_ = smu + SK_OFF + (kbuf) * SKB2; \
        const uint32_t* Q_ = smu; \
        _Pragma("unroll") \
        for (int mt_ = 0; mt_ < 2; mt_++) \
            _Pragma("unroll") \
            for (int nt_ = 0; nt_ < 4; nt_++) \
                _Pragma("unroll") \
                for (int r_ = 0; r_ < 4; r_++) S[mt_][nt_][r_] = 0.f; \
        _Pragma("unroll") \
        for (int kt_ = 0; kt_ < 4; kt_++) { \
            const int ko_ = kt_ * 8 + 2 * tg; \
            uint2 bkf_[4]; \
            _Pragma("unroll") \
            for (int nt_ = 0; nt_ < 4; nt_++) \
                bkf_[nt_] = *(const uint2*)&K_[(nt_ * 8 + gr) * QST + ko_]; \
            _Pragma("unroll") \
            for (int mt_ = 0; mt_ < 2; mt_++) { \
                const int rr_ = wq * 32 + mt_ * 16 + gr; \
                const uint2 a01_ = *(const uint2*)&Q_[rr_ * QST + ko_]; \
                const uint2 a23_ = *(const uint2*)&Q_[(rr_ + 8) * QST + ko_]; \
                uint32_t aq_[4] = {a01_.x, a23_.x, a01_.y, a23_.y}; \
                _Pragma("unroll") \
                for (int nt_ = 0; nt_ < 4; nt_++) \
                    mma_f16(S[mt_][nt_], aq_, (const uint32_t*)&bkf_[nt_]); \
            } \
        } \
    } while (0)

    // stage Q (8 chunks/thread) then first K/V tile
    {
#pragma unroll
        for (int j = 0; j < 8; j++) {
            const int f = tid + j * 128;
            const int r = f >> 3, c = (f & 7) * 4;
            CP16(smb + (uint32_t)(r * QST + c) * 4, Qp + (size_t)r * 32 + c);
        }
        CPCOMMIT();
    }
    KISSUE(0, 0, 0);

    float Of[2][8][4];
#pragma unroll
    for (int mt = 0; mt < 2; mt++)
#pragma unroll
        for (int nt = 0; nt < 8; nt++)
#pragma unroll
            for (int r = 0; r < 4; r++) Of[mt][nt][r] = 0.f;
    float m_[2][2] = {{-1e30f, -1e30f}, {-1e30f, -1e30f}};
    float l_[2][2] = {{0.f, 0.f}, {0.f, 0.f}};
    float Sc[2][4][4], Sn[2][4][4];

    const int ntiles = qt * 4 + 4;
    const int my_last = qt * 4 + wq;

    CPWAIT(0);
    __syncthreads();
    KISSUE(1, 1, 32);
    QK_TILE(Sc, 0);

    for (int it = 0; it < ntiles; it++) {
        CPWAIT(0);
        __syncthreads();
        if (it + 2 < ntiles) KISSUE((it + 2) & 1, (it + 2) % 3, (it + 2) * 32);

        const bool more = (it + 1 < ntiles) && (it + 1 <= my_last);
        if (more) QK_TILE(Sn, (it + 1) & 1);

        if (it <= my_last) {
            if (it == my_last) {
                const int t0k = it * 32;
#pragma unroll
                for (int mt = 0; mt < 2; mt++) {
                    const int r0 = q0 + wq * 32 + mt * 16 + gr;
#pragma unroll
                    for (int nt = 0; nt < 4; nt++) {
                        const int key = t0k + nt * 8 + 2 * tg;
                        if (key > r0)         Sc[mt][nt][0] = -1e30f;
                        if (key + 1 > r0)     Sc[mt][nt][1] = -1e30f;
                        if (key > r0 + 8)     Sc[mt][nt][2] = -1e30f;
                        if (key + 1 > r0 + 8) Sc[mt][nt][3] = -1e30f;
                    }
                }
            }

            // online softmax (log2 domain, fp32)
#pragma unroll
            for (int mt = 0; mt < 2; mt++)
#pragma unroll
                for (int h = 0; h < 2; h++) {
                    float tm = fmaxf(fmaxf(Sc[mt][0][2*h], Sc[mt][0][2*h+1]),
                                     fmaxf(Sc[mt][1][2*h], Sc[mt][1][2*h+1]));
                    tm = fmaxf(tm, fmaxf(fmaxf(Sc[mt][2][2*h], Sc[mt][2][2*h+1]),
                                         fmaxf(Sc[mt][3][2*h], Sc[mt][3][2*h+1])));
                    tm = fmaxf(tm, __shfl_xor_sync(0xffffffffu, tm, 1));
                    tm = fmaxf(tm, __shfl_xor_sync(0xffffffffu, tm, 2));
                    const float mnew = fmaxf(m_[mt][h], tm);
                    const float corr = exp2f(m_[mt][h] - mnew);
                    m_[mt][h] = mnew;
                    l_[mt][h] *= corr;
#pragma unroll
                    for (int nt = 0; nt < 8; nt++) {
                        Of[mt][nt][2*h]     *= corr;
                        Of[mt][nt][2*h + 1] *= corr;
                    }
                }

            float rs[2][2] = {{0.f, 0.f}, {0.f, 0.f}};
#pragma unroll
            for (int mt = 0; mt < 2; mt++)
#pragma unroll
                for (int nt = 0; nt < 4; nt++) {
                    const float p0 = exp2f(Sc[mt][nt][0] - m_[mt][0]);
                    const float p1 = exp2f(Sc[mt][nt][1] - m_[mt][0]);
                    const float p2 = exp2f(Sc[mt][nt][2] - m_[mt][1]);
                    const float p3 = exp2f(Sc[mt][nt][3] - m_[mt][1]);
                    rs[mt][0] += p0 + p1;
                    rs[mt][1] += p2 + p3;
                    Sc[mt][nt][0] = p0; Sc[mt][nt][1] = p1;
                    Sc[mt][nt][2] = p2; Sc[mt][nt][3] = p3;
                }
#pragma unroll
            for (int mt = 0; mt < 2; mt++)
#pragma unroll
                for (int h = 0; h < 2; h++) {
                    float r = rs[mt][h];
                    r += __shfl_xor_sync(0xffffffffu, r, 1);
                    r += __shfl_xor_sync(0xffffffffu, r, 2);
                    l_[mt][h] += r;
                }

            // P @ V : P packed straight from C-fragments (no shuffles)
            const uint32_t* V_ = smu + SV_OFF + (it % 3) * SVB;
#pragma unroll
            for (int j = 0; j < 2; j++) {
                uint32_t ap[2][4];
#pragma unroll
                for (int mt = 0; mt < 2; mt++) {
                    ap[mt][0] = h2pack(Sc[mt][2*j][0],   Sc[mt][2*j][1]);
                    ap[mt][1] = h2pack(Sc[mt][2*j][2],   Sc[mt][2*j][3]);
                    ap[mt][2] = h2pack(Sc[mt][2*j+1][0], Sc[mt][2*j+1][1]);
                    ap[mt][3] = h2pack(Sc[mt][2*j+1][2], Sc[mt][2*j+1][3]);
                }
#pragma unroll
                for (int ntd = 0; ntd < 8; ntd++) {
                    uint32_t bv[2];
                    bv[0] = V_[(8*j + tg) * VST2 + ntd * 8 + gr];
                    bv[1] = V_[(8*j + tg + 4) * VST2 + ntd * 8 + gr];
                    mma_f16(Of[0][ntd], ap[0], bv);
                    mma_f16(Of[1][ntd], ap[1], bv);
                }
            }
        }

#pragma unroll
        for (int mt = 0; mt < 2; mt++)
#pragma unroll
            for (int nt = 0; nt < 4; nt++)
#pragma unroll
                for (int r = 0; r < 4; r++) Sc[mt][nt][r] = Sn[mt][nt][r];
    }
#undef KISSUE
#undef QK_TILE

    // epilogue -> concat, half pair-interleaved along d
    float inv[2][2];
#pragma unroll
    for (int mt = 0; mt < 2; mt++) {
        inv[mt][0] = 1.f / l_[mt][0];
        inv[mt][1] = 1.f / l_[mt][1];
    }
    const int b_ = bh >> 4, h_ = bh & 15;
#pragma unroll
    for (int mt = 0; mt < 2; mt++) {
        const int r0 = q0 + wq * 32 + mt * 16 + gr;
        uint32_t* o0 = g_scratch + OFF_CAT + ((size_t)(b_ * Ss + r0)) * 512 + h_ * 32;
        uint32_t* o1 = g_scratch + OFF_CAT + ((size_t)(b_ * Ss + r0 + 8)) * 512 + h_ * 32;
#pragma unroll
        for (int ntd = 0; ntd < 8; ntd++) {
            const int q_l = (ntd & 1) * 4 + tg;
            const int upos = (ntd >> 1) * 8 + 2 * (q_l & 3) + (q_l >> 2);
            o0[upos] = h2pack(Of[mt][ntd][0] * inv[mt][0],
                              Of[mt][ntd][1] * inv[mt][0]);
            o1[upos] = h2pack(Of[mt][ntd][2] * inv[mt][1],
                              Of[mt][ntd][3] * inv[mt][1]);
        }
    }
}

// ---------------------------------------------------------------------------
extern "C" void kernel_launch(void* const* d_in, const int* in_sizes, int n_in,
                              void* d_out, int out_size)
{
    const float* q_in = (const float*)d_in[0];
    const float* k_in = (const float*)d_in[1];
    const float* v_in = (const float*)d_in[2];
    const float* Wq   = (const float*)d_in[3];
    const float* bq   = (const float*)d_in[4];
    const float* Wk   = (const float*)d_in[5];
    const float* bk   = (const float*)d_in[6];
    const float* Wv   = (const float*)d_in[7];
    const float* bv   = (const float*)d_in[8];
    const float* Wo   = (const float*)d_in[9];
    const float* bo   = (const float*)d_in[10];
    float* out = (float*)d_out;

    cudaFuncSetAttribute(gemm_qkv_mma_kernel,
                         cudaFuncAttributeMaxDynamicSharedMemorySize, GEMM_SMEM_BYTES);
    cudaFuncSetAttribute(gemm_out_mma_kernel,
                         cudaFuncAttributeMaxDynamicSharedMemorySize, GEMM_SMEM_BYTES);
    cudaFuncSetAttribute(attn_mma_kernel,
                         cudaFuncAttributeMaxDynamicSharedMemorySize, ATTN_SMEM_BYTES);

    round_inputs_kernel<<<dim3(QKV_ELEMS / 4096, 3), 256>>>(q_in, k_in, v_in);
    transpose_w_kernel<<<dim3(32, 32, 4), dim3(32, 8)>>>(Wq, Wk, Wv, Wo);

    gemm_qkv_mma_kernel<<<dim3(8, 16, 3), 256, GEMM_SMEM_BYTES>>>(bq, bk, bv);

    repack_v_kernel<<<(Bb * Hh * Ss / 2) * 32 / 256, 256>>>();

    attn_mma_kernel<<<512, 128, ATTN_SMEM_BYTES>>>();

    gemm_out_mma_kernel<<<dim3(8, 16), 256, GEMM_SMEM_BYTES>>>(bo, out);
}